// round 5
// baseline (speedup 1.0000x reference)
#include <cuda_runtime.h>
#include <cuda_bf16.h>
#include <math.h>

#define NN 50000
#define DD 128
#define HH 8
#define DHH 16
#define EE 800000
#define DFF 512
#define NBLK_SCAN 196   // ceil(50000/256)

// ---------------- scratch (static device globals; no allocation) ----------------
__device__ float g_z[NN * DD];
__device__ float g_wt[DD * DD];
__device__ float g_el[NN * HH];
__device__ float g_er[NN * HH];
__device__ float g_ws[EE * HH];
__device__ int   g_srcs[EE];
__device__ int   g_deg[NN];
__device__ int   g_cursor[NN];
__device__ int   g_base[NN];
__device__ int   g_bsum[256];
__device__ int   g_boff[256];
__device__ float g_hagg[NN * DD];
__device__ float g_hres[NN * DD];
__device__ float g_ln[NN * DD];
__device__ float g_inter[NN * DFF];

// ---------------- zero init (counters only) ----------------
__global__ void zero_kernel() {
    int i = blockIdx.x * blockDim.x + threadIdx.x;
    if (i < NN) { g_deg[i] = 0; g_cursor[i] = 0; }
}

// ---------------- W_fc transpose: [H,D,DH] -> [D, H*DH] ----------------
__global__ void transpose_wfc(const float* __restrict__ wfc) {
    int idx = blockIdx.x * blockDim.x + threadIdx.x;
    if (idx >= DD * DD) return;
    int h = idx >> 11;
    int d = (idx >> 4) & 127;
    int k = idx & 15;
    g_wt[d * DD + h * DHH + k] = wfc[idx];
}

// ---------------- tf32 helpers ----------------
__device__ __forceinline__ unsigned f2tf(float f) {
    unsigned u;
    asm("cvt.rna.tf32.f32 %0, %1;" : "=r"(u) : "f"(f));
    return u;
}
__device__ __forceinline__ void mma_tf32(float* c, const unsigned* a, const unsigned* b) {
    asm volatile(
        "mma.sync.aligned.m16n8k8.row.col.f32.tf32.tf32.f32 "
        "{%0,%1,%2,%3}, {%4,%5,%6,%7}, {%8,%9}, {%0,%1,%2,%3};"
        : "+f"(c[0]), "+f"(c[1]), "+f"(c[2]), "+f"(c[3])
        : "r"(a[0]), "r"(a[1]), "r"(a[2]), "r"(a[3]), "r"(b[0]), "r"(b[1]));
}

// Fragment-ordered smem layouts
#define A_G_STRIDE 1028   // 8 t-groups * 32 lanes * 4 + 4 pad
#define B_U_STRIDE 66     // 32 lanes * 2 + 2 pad
#define AF_WORDS (4 * A_G_STRIDE)        // one buffer
#define BF_WORDS (4 * 16 * B_U_STRIDE)   // one buffer
#define SMEM_WORDS (2 * AF_WORDS + 2 * BF_WORDS)
#define SMEM_BYTES (SMEM_WORDS * 4)

// ---------------- tf32 tensor-core GEMM, 128x128 tile, smem double-buffer ---------
// EPI: 0 = plain store, 1 = relu(acc + bias), 2 = acc + bias + res
template <int EPI>
__global__ void __launch_bounds__(256) tgemm_kernel(
    const float* __restrict__ A, const float* __restrict__ B, float* __restrict__ C,
    int M, int Nn, int K, const float* __restrict__ bias, const float* __restrict__ res)
{
    extern __shared__ unsigned sdyn[];
    unsigned* AfB[2] = { sdyn, sdyn + AF_WORDS };
    unsigned* BfB[2] = { sdyn + 2 * AF_WORDS, sdyn + 2 * AF_WORDS + BF_WORDS };

    const int tid = threadIdx.x;
    const int lane = tid & 31;
    const int wid = tid >> 5;
    const int wm = wid >> 2;      // 0..1
    const int wn = wid & 3;       // 0..3
    const int m0 = blockIdx.x * 128;
    const int n0 = blockIdx.y * 128;

    // loader coords
    const int a_m = tid >> 3;            // 0..31 base row (stride 32 via it)
    const int a_kq = tid & 7;            // float4 index in k
    const int b_k = tid >> 5;            // 0..7 base k (stride 8 via it)
    const int b_nq = tid & 31;           // float4 index in n

    float4 ar[4], br[4];

    auto ldg_chunk = [&](int k0) {
#pragma unroll
        for (int it = 0; it < 4; ++it) {
            int ml = a_m + it * 32;
            ar[it] = make_float4(0.f, 0.f, 0.f, 0.f);
            if (m0 + ml < M) ar[it] = *(const float4*)&A[(size_t)(m0 + ml) * K + k0 + a_kq * 4];
        }
#pragma unroll
        for (int it = 0; it < 4; ++it) {
            int kk = b_k + it * 8;
            br[it] = *(const float4*)&B[(size_t)(k0 + kk) * Nn + n0 + b_nq * 4];
        }
    };

    auto sts_chunk = [&](unsigned* Af, unsigned* Bf) {
#pragma unroll
        for (int it = 0; it < 4; ++it) {
            int ml = a_m + it * 32;
            int t = ml >> 4;
            int mr = ml & 15;
            float v[4] = {ar[it].x, ar[it].y, ar[it].z, ar[it].w};
#pragma unroll
            for (int j = 0; j < 4; ++j) {
                int kk = a_kq * 4 + j;
                int g = kk >> 3, kl = kk & 7;
                int lw = (mr & 7) * 4 + (kl & 3);
                int iw = (mr >> 3) + 2 * (kl >> 2);
                Af[g * A_G_STRIDE + t * 128 + lw * 4 + iw] = f2tf(v[j]);
            }
        }
#pragma unroll
        for (int it = 0; it < 4; ++it) {
            int kk = b_k + it * 8;
            int g = kk >> 3, kl = kk & 7;
            float v[4] = {br[it].x, br[it].y, br[it].z, br[it].w};
#pragma unroll
            for (int j = 0; j < 4; ++j) {
                int nn = b_nq * 4 + j;
                int u = nn >> 3, nl = nn & 7;
                int lw = nl * 4 + (kl & 3);
                int iw = kl >> 2;
                Bf[(g * 16 + u) * B_U_STRIDE + lw * 2 + iw] = f2tf(v[j]);
            }
        }
    };

    float acc[4][4][4];
#pragma unroll
    for (int i = 0; i < 4; ++i)
#pragma unroll
        for (int j = 0; j < 4; ++j)
#pragma unroll
            for (int r = 0; r < 4; ++r) acc[i][j][r] = 0.f;

    auto mma_chunk = [&](const unsigned* Af, const unsigned* Bf) {
#pragma unroll
        for (int g = 0; g < 4; ++g) {
            unsigned af[4][4], bf[4][2];
#pragma unroll
            for (int mt = 0; mt < 4; ++mt)
                *(uint4*)af[mt] = *(const uint4*)&Af[g * A_G_STRIDE + (wm * 4 + mt) * 128 + lane * 4];
#pragma unroll
            for (int nt = 0; nt < 4; ++nt)
                *(uint2*)bf[nt] = *(const uint2*)&Bf[(g * 16 + wn * 4 + nt) * B_U_STRIDE + lane * 2];
#pragma unroll
            for (int mt = 0; mt < 4; ++mt)
#pragma unroll
                for (int nt = 0; nt < 4; ++nt)
                    mma_tf32(acc[mt][nt], af[mt], bf[nt]);
        }
    };

    const int CHUNKS = K >> 5;
    ldg_chunk(0);
    sts_chunk(AfB[0], BfB[0]);
    __syncthreads();
    for (int c = 1; c < CHUNKS; ++c) {
        ldg_chunk(c * 32);
        mma_chunk(AfB[(c - 1) & 1], BfB[(c - 1) & 1]);
        sts_chunk(AfB[c & 1], BfB[c & 1]);
        __syncthreads();
    }
    mma_chunk(AfB[(CHUNKS - 1) & 1], BfB[(CHUNKS - 1) & 1]);

    // epilogue
    const int lr = lane >> 2;
    const int lc = lane & 3;
#pragma unroll
    for (int mt = 0; mt < 4; ++mt) {
#pragma unroll
        for (int nt = 0; nt < 4; ++nt) {
            int row = m0 + wm * 64 + mt * 16 + lr;
            int col = n0 + wn * 32 + nt * 8 + 2 * lc;
            float c0 = acc[mt][nt][0], c1 = acc[mt][nt][1];
            float c2 = acc[mt][nt][2], c3 = acc[mt][nt][3];
            if (EPI == 1) {
                float b0 = bias[col], b1 = bias[col + 1];
                c0 = fmaxf(c0 + b0, 0.f); c1 = fmaxf(c1 + b1, 0.f);
                c2 = fmaxf(c2 + b0, 0.f); c3 = fmaxf(c3 + b1, 0.f);
            }
            if (EPI == 2) {
                float b0 = bias[col], b1 = bias[col + 1];
                if (row < M) {
                    c0 += b0 + res[(size_t)row * Nn + col];
                    c1 += b1 + res[(size_t)row * Nn + col + 1];
                }
                if (row + 8 < M) {
                    c2 += b0 + res[(size_t)(row + 8) * Nn + col];
                    c3 += b1 + res[(size_t)(row + 8) * Nn + col + 1];
                }
            }
            if (row < M)     *(float2*)&C[(size_t)row * Nn + col]       = make_float2(c0, c1);
            if (row + 8 < M) *(float2*)&C[(size_t)(row + 8) * Nn + col] = make_float2(c2, c3);
        }
    }
}

// ---------------- el / er: one thread per (node, head) ----------------
__global__ void eler_kernel(const float* __restrict__ a_l, const float* __restrict__ a_r) {
    int idx = blockIdx.x * blockDim.x + threadIdx.x;
    if (idx >= NN * HH) return;
    int n = idx >> 3;
    int h = idx & 7;
    const float4* zp = (const float4*)&g_z[n * DD + h * DHH];
    const float4* lp = (const float4*)&a_l[h * DHH];
    const float4* rp = (const float4*)&a_r[h * DHH];
    float pl = 0.f, pr = 0.f;
#pragma unroll
    for (int q = 0; q < 4; ++q) {
        float4 z = zp[q], l = lp[q], r = rp[q];
        pl += z.x * l.x + z.y * l.y + z.z * l.z + z.w * l.w;
        pr += z.x * r.x + z.y * r.y + z.z * r.z + z.w * r.w;
    }
    g_el[idx] = pl;
    g_er[idx] = pr;
}

// ---------------- degree histogram ----------------
__global__ void deg_kernel(const int* __restrict__ edst) {
    int e = blockIdx.x * blockDim.x + threadIdx.x;
    if (e >= EE) return;
    atomicAdd(&g_deg[edst[e]], 1);
}

// ---------------- exclusive scan over deg ----------------
__global__ void scan1_kernel() {
    __shared__ int sh[256];
    int t = threadIdx.x;
    int i = blockIdx.x * 256 + t;
    int v = (i < NN) ? g_deg[i] : 0;
    sh[t] = v;
    __syncthreads();
#pragma unroll
    for (int off = 1; off < 256; off <<= 1) {
        int x = (t >= off) ? sh[t - off] : 0;
        __syncthreads();
        sh[t] += x;
        __syncthreads();
    }
    if (i < NN) g_base[i] = sh[t] - v;
    if (t == 255) g_bsum[blockIdx.x] = sh[255];
}
__global__ void scan2_kernel() {
    __shared__ int sh[256];
    int t = threadIdx.x;
    int v = (t < NBLK_SCAN) ? g_bsum[t] : 0;
    sh[t] = v;
    __syncthreads();
#pragma unroll
    for (int off = 1; off < 256; off <<= 1) {
        int x = (t >= off) ? sh[t - off] : 0;
        __syncthreads();
        sh[t] += x;
        __syncthreads();
    }
    g_boff[t] = sh[t] - v;
}
__global__ void scan3_kernel() {
    int i = blockIdx.x * blockDim.x + threadIdx.x;
    if (i < NN) g_base[i] += g_boff[i >> 8];
}

// ---------------- scatter edges into CSR slots + compute head weights ----------------
__global__ void scatter_kernel(const int* __restrict__ esrc, const int* __restrict__ edst) {
    int e = blockIdx.x * blockDim.x + threadIdx.x;
    if (e >= EE) return;
    int s = esrc[e], d = edst[e];
    int pos = g_base[d] + atomicAdd(&g_cursor[d], 1);
    g_srcs[pos] = s;
    float4 el0 = *(const float4*)&g_el[s * HH];
    float4 el1 = *(const float4*)&g_el[s * HH + 4];
    float4 er0 = *(const float4*)&g_er[d * HH];
    float4 er1 = *(const float4*)&g_er[d * HH + 4];
    float ev[8] = {el0.x + er0.x, el0.y + er0.y, el0.z + er0.z, el0.w + er0.w,
                   el1.x + er1.x, el1.y + er1.y, el1.z + er1.z, el1.w + er1.w};
    float w[8];
#pragma unroll
    for (int h = 0; h < 8; ++h) {
        float v = ev[h];
        v = (v > 0.f) ? v : 0.01f * v;
        w[h] = __expf(v);
    }
    *(float4*)&g_ws[(size_t)pos * HH]     = make_float4(w[0], w[1], w[2], w[3]);
    *(float4*)&g_ws[(size_t)pos * HH + 4] = make_float4(w[4], w[5], w[6], w[7]);
}

// ---------------- warp-per-node aggregation (no atomics) ----------------
__global__ void __launch_bounds__(256) agg_kernel() {
    int n = blockIdx.x * 8 + (threadIdx.x >> 5);
    int lane = threadIdx.x & 31;
    if (n >= NN) return;
    int start = g_base[n];
    int deg = g_deg[n];
    float4 acc = make_float4(0.f, 0.f, 0.f, 0.f);
    if (deg > 0) {
        float s0 = 0.f, s1 = 0.f, s2 = 0.f, s3 = 0.f;
        float s4 = 0.f, s5 = 0.f, s6 = 0.f, s7 = 0.f;
        for (int i = start + lane; i < start + deg; i += 32) {
            float4 wa = *(const float4*)&g_ws[(size_t)i * HH];
            float4 wb = *(const float4*)&g_ws[(size_t)i * HH + 4];
            s0 += wa.x; s1 += wa.y; s2 += wa.z; s3 += wa.w;
            s4 += wb.x; s5 += wb.y; s6 += wb.z; s7 += wb.w;
        }
#pragma unroll
        for (int o = 16; o >= 1; o >>= 1) {
            s0 += __shfl_xor_sync(0xffffffffu, s0, o);
            s1 += __shfl_xor_sync(0xffffffffu, s1, o);
            s2 += __shfl_xor_sync(0xffffffffu, s2, o);
            s3 += __shfl_xor_sync(0xffffffffu, s3, o);
            s4 += __shfl_xor_sync(0xffffffffu, s4, o);
            s5 += __shfl_xor_sync(0xffffffffu, s5, o);
            s6 += __shfl_xor_sync(0xffffffffu, s6, o);
            s7 += __shfl_xor_sync(0xffffffffu, s7, o);
        }
        int h = lane >> 2;
        float sv;
        switch (h) {
            case 0: sv = s0; break;
            case 1: sv = s1; break;
            case 2: sv = s2; break;
            case 3: sv = s3; break;
            case 4: sv = s4; break;
            case 5: sv = s5; break;
            case 6: sv = s6; break;
            default: sv = s7; break;
        }
        float inv = 1.f / fmaxf(sv, 1e-9f);
        for (int i = start; i < start + deg; ++i) {
            int src = g_srcs[i];
            float alpha = g_ws[(size_t)i * HH + h] * inv;
            float4 zv = *(const float4*)&g_z[(size_t)src * DD + lane * 4];
            acc.x = fmaf(alpha, zv.x, acc.x);
            acc.y = fmaf(alpha, zv.y, acc.y);
            acc.z = fmaf(alpha, zv.z, acc.z);
            acc.w = fmaf(alpha, zv.w, acc.w);
        }
    }
    *(float4*)&g_hagg[(size_t)n * DD + lane * 4] = acc;
}

// ---------------- elu + residual + LayerNorm (warp per node) ----------------
__global__ void ln_kernel(const float* __restrict__ x,
                          const float* __restrict__ gamma, const float* __restrict__ beta) {
    int warp = threadIdx.x >> 5;
    int lane = threadIdx.x & 31;
    int n = blockIdx.x * 8 + warp;
    if (n >= NN) return;
    float4 hv = ((const float4*)(g_hagg + n * DD))[lane];
    float4 xv = ((const float4*)(x + n * DD))[lane];
    float4 r;
    r.x = xv.x + (hv.x > 0.f ? hv.x : expm1f(hv.x));
    r.y = xv.y + (hv.y > 0.f ? hv.y : expm1f(hv.y));
    r.z = xv.z + (hv.z > 0.f ? hv.z : expm1f(hv.z));
    r.w = xv.w + (hv.w > 0.f ? hv.w : expm1f(hv.w));
    ((float4*)(g_hres + n * DD))[lane] = r;
    float sum = r.x + r.y + r.z + r.w;
    float sq = r.x * r.x + r.y * r.y + r.z * r.z + r.w * r.w;
#pragma unroll
    for (int o = 16; o >= 1; o >>= 1) {
        sum += __shfl_xor_sync(0xffffffffu, sum, o);
        sq  += __shfl_xor_sync(0xffffffffu, sq, o);
    }
    float mu = sum * (1.f / 128.f);
    float var = sq * (1.f / 128.f) - mu * mu;
    float rstd = rsqrtf(var + 1e-5f);
    float4 gv = ((const float4*)gamma)[lane];
    float4 bv = ((const float4*)beta)[lane];
    float4 o;
    o.x = (r.x - mu) * rstd * gv.x + bv.x;
    o.y = (r.y - mu) * rstd * gv.y + bv.y;
    o.z = (r.z - mu) * rstd * gv.z + bv.z;
    o.w = (r.w - mu) * rstd * gv.w + bv.w;
    ((float4*)(g_ln + n * DD))[lane] = o;
}

// ---------------- launch ----------------
extern "C" void kernel_launch(void* const* d_in, const int* in_sizes, int n_in,
                              void* d_out, int out_size) {
    const float* x      = (const float*)d_in[0];
    const float* wfc    = (const float*)d_in[1];
    const float* a_l    = (const float*)d_in[2];
    const float* a_r    = (const float*)d_in[3];
    const float* gamma  = (const float*)d_in[4];
    const float* beta   = (const float*)d_in[5];
    const float* W1     = (const float*)d_in[6];
    const float* b1     = (const float*)d_in[7];
    const float* W2     = (const float*)d_in[8];
    const float* b2     = (const float*)d_in[9];
    const int* esrc     = (const int*)d_in[10];
    const int* edst     = (const int*)d_in[11];
    float* out          = (float*)d_out;

    float *p_z, *p_wt, *p_ln, *p_inter, *p_hres;
    cudaGetSymbolAddress((void**)&p_z, g_z);
    cudaGetSymbolAddress((void**)&p_wt, g_wt);
    cudaGetSymbolAddress((void**)&p_ln, g_ln);
    cudaGetSymbolAddress((void**)&p_inter, g_inter);
    cudaGetSymbolAddress((void**)&p_hres, g_hres);

    static int smem_set = 0;
    if (!smem_set) {
        cudaFuncSetAttribute(tgemm_kernel<0>, cudaFuncAttributeMaxDynamicSharedMemorySize, SMEM_BYTES);
        cudaFuncSetAttribute(tgemm_kernel<1>, cudaFuncAttributeMaxDynamicSharedMemorySize, SMEM_BYTES);
        cudaFuncSetAttribute(tgemm_kernel<2>, cudaFuncAttributeMaxDynamicSharedMemorySize, SMEM_BYTES);
        smem_set = 1;
    }

    // launch order: slot 4 (1-indexed) = tgemm so ncu profiles the GEMM
    zero_kernel<<<(NN + 255) / 256, 256>>>();
    transpose_wfc<<<(DD * DD + 255) / 256, 256>>>(wfc);
    deg_kernel<<<(EE + 255) / 256, 256>>>(edst);

    // z = x @ WT
    {
        dim3 grid((NN + 127) / 128, 1);
        tgemm_kernel<0><<<grid, 256, SMEM_BYTES>>>(x, p_wt, p_z, NN, DD, DD, nullptr, nullptr);
    }
    eler_kernel<<<(NN * HH + 255) / 256, 256>>>(a_l, a_r);

    scan1_kernel<<<NBLK_SCAN, 256>>>();
    scan2_kernel<<<1, 256>>>();
    scan3_kernel<<<(NN + 255) / 256, 256>>>();
    scatter_kernel<<<(EE + 255) / 256, 256>>>(esrc, edst);

    agg_kernel<<<(NN + 7) / 8, 256>>>();
    ln_kernel<<<(NN + 7) / 8, 256>>>(x, gamma, beta);

    // inter = relu(ln @ W1 + b1)
    {
        dim3 grid((NN + 127) / 128, DFF / 128);
        tgemm_kernel<1><<<grid, 256, SMEM_BYTES>>>(p_ln, W1, p_inter, NN, DFF, DD, b1, nullptr);
    }
    // out = inter @ W2 + b2 + hres
    {
        dim3 grid((NN + 127) / 128, 1);
        tgemm_kernel<2><<<grid, 256, SMEM_BYTES>>>(p_inter, W2, out, NN, DD, DFF, b2, p_hres);
    }
}

// round 6
// speedup vs baseline: 1.0909x; 1.0909x over previous
#include <cuda_runtime.h>
#include <cuda_bf16.h>
#include <math.h>

#define NN 50000
#define DD 128
#define HH 8
#define DHH 16
#define EE 800000
#define DFF 512
#define NBLK_SCAN 196   // ceil(50000/256)

// ---------------- scratch (static device globals; no allocation) ----------------
__device__ float g_z[NN * DD];
__device__ float g_wt[DD * DD];
__device__ float g_el[NN * HH];
__device__ float g_er[NN * HH];
__device__ float g_ws[EE * HH];
__device__ int   g_srcs[EE];
__device__ int   g_deg[NN];
__device__ int   g_cursor[NN];
__device__ int   g_base[NN];
__device__ int   g_bsum[256];
__device__ int   g_boff[256];
__device__ float g_hagg[NN * DD];
__device__ float g_hres[NN * DD];
__device__ float g_ln[NN * DD];
__device__ float g_inter[NN * DFF];

// ---------------- zero init (counters only) ----------------
__global__ void zero_kernel() {
    int i = blockIdx.x * blockDim.x + threadIdx.x;
    if (i < NN) { g_deg[i] = 0; g_cursor[i] = 0; }
}

// ---------------- W_fc transpose: [H,D,DH] -> [D, H*DH] ----------------
__global__ void transpose_wfc(const float* __restrict__ wfc) {
    int idx = blockIdx.x * blockDim.x + threadIdx.x;
    if (idx >= DD * DD) return;
    int h = idx >> 11;
    int d = (idx >> 4) & 127;
    int k = idx & 15;
    g_wt[d * DD + h * DHH + k] = wfc[idx];
}

// ---------------- tf32 helpers ----------------
__device__ __forceinline__ unsigned f2tf(float f) {
    unsigned u;
    asm("cvt.rna.tf32.f32 %0, %1;" : "=r"(u) : "f"(f));
    return u;
}
__device__ __forceinline__ void mma_tf32(float* c, const unsigned* a, const unsigned* b) {
    asm volatile(
        "mma.sync.aligned.m16n8k8.row.col.f32.tf32.tf32.f32 "
        "{%0,%1,%2,%3}, {%4,%5,%6,%7}, {%8,%9}, {%0,%1,%2,%3};"
        : "+f"(c[0]), "+f"(c[1]), "+f"(c[2]), "+f"(c[3])
        : "r"(a[0]), "r"(a[1]), "r"(a[2]), "r"(a[3]), "r"(b[0]), "r"(b[1]));
}

// Fragment-ordered smem layouts (64x64 tile)
#define A_G_STRIDE 516    // 4 t-groups (64 rows) * 128 + 4 pad
#define B_U_STRIDE 66     // 32 lanes * 2 + 2 pad

// ---------------- tf32 tensor-core GEMM, 64x64 tile, 128 threads -----------------
// EPI: 0 = plain store, 1 = relu(acc + bias), 2 = acc + bias + res
template <int EPI>
__global__ void __launch_bounds__(128, 4) tgemm_kernel(
    const float* __restrict__ A, const float* __restrict__ B, float* __restrict__ C,
    int M, int Nn, int K, const float* __restrict__ bias, const float* __restrict__ res)
{
    __shared__ unsigned Af[4 * A_G_STRIDE];       // 4 k8-groups x 64 rows
    __shared__ unsigned Bf[4 * 8 * B_U_STRIDE];   // 4 k8-groups x 8 n8-groups

    const int tid = threadIdx.x;
    const int lane = tid & 31;
    const int wid = tid >> 5;
    const int wm = wid >> 1;      // 0..1
    const int wn = wid & 1;       // 0..1
    const int m0 = blockIdx.x * 64;
    const int n0 = blockIdx.y * 64;

    // loader coords
    const int a_m = tid >> 3;            // 0..15 base row (stride 16 via it)
    const int a_kq = tid & 7;            // float4 index in k
    const int b_k = tid >> 4;            // 0..7 base k (stride 8 via it)
    const int b_nq = tid & 15;           // float4 index in n (64 n)

    float4 ar[4], br[4];

    auto ldg_chunk = [&](int k0) {
#pragma unroll
        for (int it = 0; it < 4; ++it) {
            int ml = a_m + it * 16;
            ar[it] = make_float4(0.f, 0.f, 0.f, 0.f);
            if (m0 + ml < M) ar[it] = *(const float4*)&A[(size_t)(m0 + ml) * K + k0 + a_kq * 4];
        }
#pragma unroll
        for (int it = 0; it < 4; ++it) {
            int kk = b_k + it * 8;
            br[it] = *(const float4*)&B[(size_t)(k0 + kk) * Nn + n0 + b_nq * 4];
        }
    };

    auto sts_chunk = [&]() {
#pragma unroll
        for (int it = 0; it < 4; ++it) {
            int ml = a_m + it * 16;
            int t = ml >> 4;
            int mr = ml & 15;
            float v[4] = {ar[it].x, ar[it].y, ar[it].z, ar[it].w};
#pragma unroll
            for (int j = 0; j < 4; ++j) {
                int kk = a_kq * 4 + j;
                int g = kk >> 3, kl = kk & 7;
                int lw = (mr & 7) * 4 + (kl & 3);
                int iw = (mr >> 3) + 2 * (kl >> 2);
                Af[g * A_G_STRIDE + t * 128 + lw * 4 + iw] = f2tf(v[j]);
            }
        }
#pragma unroll
        for (int it = 0; it < 4; ++it) {
            int kk = b_k + it * 8;
            int g = kk >> 3, kl = kk & 7;
            float v[4] = {br[it].x, br[it].y, br[it].z, br[it].w};
#pragma unroll
            for (int j = 0; j < 4; ++j) {
                int nn = b_nq * 4 + j;
                int u = nn >> 3, nl = nn & 7;
                int lw = nl * 4 + (kl & 3);
                int iw = kl >> 2;
                Bf[(g * 8 + u) * B_U_STRIDE + lw * 2 + iw] = f2tf(v[j]);
            }
        }
    };

    float acc[2][4][4];
#pragma unroll
    for (int i = 0; i < 2; ++i)
#pragma unroll
        for (int j = 0; j < 4; ++j)
#pragma unroll
            for (int r = 0; r < 4; ++r) acc[i][j][r] = 0.f;

    auto mma_chunk = [&]() {
#pragma unroll
        for (int g = 0; g < 4; ++g) {
            unsigned af[2][4], bf[4][2];
#pragma unroll
            for (int mt = 0; mt < 2; ++mt)
                *(uint4*)af[mt] = *(const uint4*)&Af[g * A_G_STRIDE + (wm * 2 + mt) * 128 + lane * 4];
#pragma unroll
            for (int nt = 0; nt < 4; ++nt)
                *(uint2*)bf[nt] = *(const uint2*)&Bf[(g * 8 + wn * 4 + nt) * B_U_STRIDE + lane * 2];
#pragma unroll
            for (int mt = 0; mt < 2; ++mt)
#pragma unroll
                for (int nt = 0; nt < 4; ++nt)
                    mma_tf32(acc[mt][nt], af[mt], bf[nt]);
        }
    };

    const int CHUNKS = K >> 5;
    ldg_chunk(0);
    sts_chunk();
    __syncthreads();
    for (int c = 1; c < CHUNKS; ++c) {
        ldg_chunk(c * 32);
        mma_chunk();
        __syncthreads();
        sts_chunk();
        __syncthreads();
    }
    mma_chunk();

    // epilogue
    const int lr = lane >> 2;
    const int lc = lane & 3;
#pragma unroll
    for (int mt = 0; mt < 2; ++mt) {
#pragma unroll
        for (int nt = 0; nt < 4; ++nt) {
            int row = m0 + wm * 32 + mt * 16 + lr;
            int col = n0 + wn * 32 + nt * 8 + 2 * lc;
            float c0 = acc[mt][nt][0], c1 = acc[mt][nt][1];
            float c2 = acc[mt][nt][2], c3 = acc[mt][nt][3];
            if (EPI == 1) {
                float b0 = bias[col], b1 = bias[col + 1];
                c0 = fmaxf(c0 + b0, 0.f); c1 = fmaxf(c1 + b1, 0.f);
                c2 = fmaxf(c2 + b0, 0.f); c3 = fmaxf(c3 + b1, 0.f);
            }
            if (EPI == 2) {
                float b0 = bias[col], b1 = bias[col + 1];
                if (row < M) {
                    c0 += b0 + res[(size_t)row * Nn + col];
                    c1 += b1 + res[(size_t)row * Nn + col + 1];
                }
                if (row + 8 < M) {
                    c2 += b0 + res[(size_t)(row + 8) * Nn + col];
                    c3 += b1 + res[(size_t)(row + 8) * Nn + col + 1];
                }
            }
            if (row < M)     *(float2*)&C[(size_t)row * Nn + col]       = make_float2(c0, c1);
            if (row + 8 < M) *(float2*)&C[(size_t)(row + 8) * Nn + col] = make_float2(c2, c3);
        }
    }
}

// ---------------- el / er: one thread per (node, head) ----------------
__global__ void eler_kernel(const float* __restrict__ a_l, const float* __restrict__ a_r) {
    int idx = blockIdx.x * blockDim.x + threadIdx.x;
    if (idx >= NN * HH) return;
    int n = idx >> 3;
    int h = idx & 7;
    const float4* zp = (const float4*)&g_z[n * DD + h * DHH];
    const float4* lp = (const float4*)&a_l[h * DHH];
    const float4* rp = (const float4*)&a_r[h * DHH];
    float pl = 0.f, pr = 0.f;
#pragma unroll
    for (int q = 0; q < 4; ++q) {
        float4 z = zp[q], l = lp[q], r = rp[q];
        pl += z.x * l.x + z.y * l.y + z.z * l.z + z.w * l.w;
        pr += z.x * r.x + z.y * r.y + z.z * r.z + z.w * r.w;
    }
    g_el[idx] = pl;
    g_er[idx] = pr;
}

// ---------------- degree histogram ----------------
__global__ void deg_kernel(const int* __restrict__ edst) {
    int e = blockIdx.x * blockDim.x + threadIdx.x;
    if (e >= EE) return;
    atomicAdd(&g_deg[edst[e]], 1);
}

// ---------------- exclusive scan over deg ----------------
__global__ void scan1_kernel() {
    __shared__ int sh[256];
    int t = threadIdx.x;
    int i = blockIdx.x * 256 + t;
    int v = (i < NN) ? g_deg[i] : 0;
    sh[t] = v;
    __syncthreads();
#pragma unroll
    for (int off = 1; off < 256; off <<= 1) {
        int x = (t >= off) ? sh[t - off] : 0;
        __syncthreads();
        sh[t] += x;
        __syncthreads();
    }
    if (i < NN) g_base[i] = sh[t] - v;
    if (t == 255) g_bsum[blockIdx.x] = sh[255];
}
__global__ void scan2_kernel() {
    __shared__ int sh[256];
    int t = threadIdx.x;
    int v = (t < NBLK_SCAN) ? g_bsum[t] : 0;
    sh[t] = v;
    __syncthreads();
#pragma unroll
    for (int off = 1; off < 256; off <<= 1) {
        int x = (t >= off) ? sh[t - off] : 0;
        __syncthreads();
        sh[t] += x;
        __syncthreads();
    }
    g_boff[t] = sh[t] - v;
}
__global__ void scan3_kernel() {
    int i = blockIdx.x * blockDim.x + threadIdx.x;
    if (i < NN) g_base[i] += g_boff[i >> 8];
}

// ---------------- scatter edges into CSR slots + compute head weights ----------------
__global__ void scatter_kernel(const int* __restrict__ esrc, const int* __restrict__ edst) {
    int e = blockIdx.x * blockDim.x + threadIdx.x;
    if (e >= EE) return;
    int s = esrc[e], d = edst[e];
    int pos = g_base[d] + atomicAdd(&g_cursor[d], 1);
    g_srcs[pos] = s;
    float4 el0 = *(const float4*)&g_el[s * HH];
    float4 el1 = *(const float4*)&g_el[s * HH + 4];
    float4 er0 = *(const float4*)&g_er[d * HH];
    float4 er1 = *(const float4*)&g_er[d * HH + 4];
    float ev[8] = {el0.x + er0.x, el0.y + er0.y, el0.z + er0.z, el0.w + er0.w,
                   el1.x + er1.x, el1.y + er1.y, el1.z + er1.z, el1.w + er1.w};
    float w[8];
#pragma unroll
    for (int h = 0; h < 8; ++h) {
        float v = ev[h];
        v = (v > 0.f) ? v : 0.01f * v;
        w[h] = __expf(v);
    }
    *(float4*)&g_ws[(size_t)pos * HH]     = make_float4(w[0], w[1], w[2], w[3]);
    *(float4*)&g_ws[(size_t)pos * HH + 4] = make_float4(w[4], w[5], w[6], w[7]);
}

// ---------------- warp-per-node aggregation (no atomics) ----------------
__global__ void __launch_bounds__(256) agg_kernel() {
    int n = blockIdx.x * 8 + (threadIdx.x >> 5);
    int lane = threadIdx.x & 31;
    if (n >= NN) return;
    int start = g_base[n];
    int deg = g_deg[n];
    float4 acc = make_float4(0.f, 0.f, 0.f, 0.f);
    if (deg > 0) {
        float s0 = 0.f, s1 = 0.f, s2 = 0.f, s3 = 0.f;
        float s4 = 0.f, s5 = 0.f, s6 = 0.f, s7 = 0.f;
        for (int i = start + lane; i < start + deg; i += 32) {
            float4 wa = *(const float4*)&g_ws[(size_t)i * HH];
            float4 wb = *(const float4*)&g_ws[(size_t)i * HH + 4];
            s0 += wa.x; s1 += wa.y; s2 += wa.z; s3 += wa.w;
            s4 += wb.x; s5 += wb.y; s6 += wb.z; s7 += wb.w;
        }
#pragma unroll
        for (int o = 16; o >= 1; o >>= 1) {
            s0 += __shfl_xor_sync(0xffffffffu, s0, o);
            s1 += __shfl_xor_sync(0xffffffffu, s1, o);
            s2 += __shfl_xor_sync(0xffffffffu, s2, o);
            s3 += __shfl_xor_sync(0xffffffffu, s3, o);
            s4 += __shfl_xor_sync(0xffffffffu, s4, o);
            s5 += __shfl_xor_sync(0xffffffffu, s5, o);
            s6 += __shfl_xor_sync(0xffffffffu, s6, o);
            s7 += __shfl_xor_sync(0xffffffffu, s7, o);
        }
        int h = lane >> 2;
        float sv;
        switch (h) {
            case 0: sv = s0; break;
            case 1: sv = s1; break;
            case 2: sv = s2; break;
            case 3: sv = s3; break;
            case 4: sv = s4; break;
            case 5: sv = s5; break;
            case 6: sv = s6; break;
            default: sv = s7; break;
        }
        float inv = 1.f / fmaxf(sv, 1e-9f);
        for (int i = start; i < start + deg; ++i) {
            int src = g_srcs[i];
            float alpha = g_ws[(size_t)i * HH + h] * inv;
            float4 zv = *(const float4*)&g_z[(size_t)src * DD + lane * 4];
            acc.x = fmaf(alpha, zv.x, acc.x);
            acc.y = fmaf(alpha, zv.y, acc.y);
            acc.z = fmaf(alpha, zv.z, acc.z);
            acc.w = fmaf(alpha, zv.w, acc.w);
        }
    }
    *(float4*)&g_hagg[(size_t)n * DD + lane * 4] = acc;
}

// ---------------- elu + residual + LayerNorm (warp per node) ----------------
__global__ void ln_kernel(const float* __restrict__ x,
                          const float* __restrict__ gamma, const float* __restrict__ beta) {
    int warp = threadIdx.x >> 5;
    int lane = threadIdx.x & 31;
    int n = blockIdx.x * 8 + warp;
    if (n >= NN) return;
    float4 hv = ((const float4*)(g_hagg + n * DD))[lane];
    float4 xv = ((const float4*)(x + n * DD))[lane];
    float4 r;
    r.x = xv.x + (hv.x > 0.f ? hv.x : expm1f(hv.x));
    r.y = xv.y + (hv.y > 0.f ? hv.y : expm1f(hv.y));
    r.z = xv.z + (hv.z > 0.f ? hv.z : expm1f(hv.z));
    r.w = xv.w + (hv.w > 0.f ? hv.w : expm1f(hv.w));
    ((float4*)(g_hres + n * DD))[lane] = r;
    float sum = r.x + r.y + r.z + r.w;
    float sq = r.x * r.x + r.y * r.y + r.z * r.z + r.w * r.w;
#pragma unroll
    for (int o = 16; o >= 1; o >>= 1) {
        sum += __shfl_xor_sync(0xffffffffu, sum, o);
        sq  += __shfl_xor_sync(0xffffffffu, sq, o);
    }
    float mu = sum * (1.f / 128.f);
    float var = sq * (1.f / 128.f) - mu * mu;
    float rstd = rsqrtf(var + 1e-5f);
    float4 gv = ((const float4*)gamma)[lane];
    float4 bv = ((const float4*)beta)[lane];
    float4 o;
    o.x = (r.x - mu) * rstd * gv.x + bv.x;
    o.y = (r.y - mu) * rstd * gv.y + bv.y;
    o.z = (r.z - mu) * rstd * gv.z + bv.z;
    o.w = (r.w - mu) * rstd * gv.w + bv.w;
    ((float4*)(g_ln + n * DD))[lane] = o;
}

// ---------------- launch ----------------
extern "C" void kernel_launch(void* const* d_in, const int* in_sizes, int n_in,
                              void* d_out, int out_size) {
    const float* x      = (const float*)d_in[0];
    const float* wfc    = (const float*)d_in[1];
    const float* a_l    = (const float*)d_in[2];
    const float* a_r    = (const float*)d_in[3];
    const float* gamma  = (const float*)d_in[4];
    const float* beta   = (const float*)d_in[5];
    const float* W1     = (const float*)d_in[6];
    const float* b1     = (const float*)d_in[7];
    const float* W2     = (const float*)d_in[8];
    const float* b2     = (const float*)d_in[9];
    const int* esrc     = (const int*)d_in[10];
    const int* edst     = (const int*)d_in[11];
    float* out          = (float*)d_out;

    float *p_z, *p_wt, *p_ln, *p_inter, *p_hres;
    cudaGetSymbolAddress((void**)&p_z, g_z);
    cudaGetSymbolAddress((void**)&p_wt, g_wt);
    cudaGetSymbolAddress((void**)&p_ln, g_ln);
    cudaGetSymbolAddress((void**)&p_inter, g_inter);
    cudaGetSymbolAddress((void**)&p_hres, g_hres);

    // launch order: slot 4 (1-indexed) = tgemm so ncu profiles the GEMM
    zero_kernel<<<(NN + 255) / 256, 256>>>();
    transpose_wfc<<<(DD * DD + 255) / 256, 256>>>(wfc);
    deg_kernel<<<(EE + 255) / 256, 256>>>(edst);

    // z = x @ WT
    {
        dim3 grid((NN + 63) / 64, DD / 64);
        tgemm_kernel<0><<<grid, 128>>>(x, p_wt, p_z, NN, DD, DD, nullptr, nullptr);
    }
    eler_kernel<<<(NN * HH + 255) / 256, 256>>>(a_l, a_r);

    scan1_kernel<<<NBLK_SCAN, 256>>>();
    scan2_kernel<<<1, 256>>>();
    scan3_kernel<<<(NN + 255) / 256, 256>>>();
    scatter_kernel<<<(EE + 255) / 256, 256>>>(esrc, edst);

    agg_kernel<<<(NN + 7) / 8, 256>>>();
    ln_kernel<<<(NN + 7) / 8, 256>>>(x, gamma, beta);

    // inter = relu(ln @ W1 + b1)
    {
        dim3 grid((NN + 63) / 64, DFF / 64);
        tgemm_kernel<1><<<grid, 128>>>(p_ln, W1, p_inter, NN, DFF, DD, b1, nullptr);
    }
    // out = inter @ W2 + b2 + hres
    {
        dim3 grid((NN + 63) / 64, DD / 64);
        tgemm_kernel<2><<<grid, 128>>>(p_inter, W2, out, NN, DD, DFF, b2, p_hres);
    }
}

// round 8
// speedup vs baseline: 1.3848x; 1.2694x over previous
#include <cuda_runtime.h>
#include <cuda_fp16.h>
#include <math.h>
#include <stdint.h>

#define NN 50000
#define DD 128
#define HH 8
#define DHH 16
#define EE 800000
#define DFF 512
#define NBLK_SCAN 196   // ceil(50000/256)

// ---------------- scratch (static device globals; no allocation) ----------------
__device__ float g_z[NN * DD];
__device__ float g_wt[DD * DD];
__device__ float g_el[NN * HH];
__device__ float g_er[NN * HH];
__device__ float g_ws[EE * HH];
__device__ int   g_srcs[EE];
__device__ int   g_deg[NN];
__device__ int   g_cursor[NN];
__device__ int   g_base[NN];
__device__ int   g_bsum[256];
__device__ int   g_boff[256];
__device__ float g_hagg[NN * DD];
__device__ float g_hres[NN * DD];
__device__ float g_ln[NN * DD];
__device__ float g_inter[NN * DFF];

// ---------------- zero init (counters only) ----------------
__global__ void zero_kernel() {
    int i = blockIdx.x * blockDim.x + threadIdx.x;
    if (i < NN) { g_deg[i] = 0; g_cursor[i] = 0; }
}

// ---------------- W_fc transpose: [H,D,DH] -> [D, H*DH] ----------------
__global__ void transpose_wfc(const float* __restrict__ wfc) {
    int idx = blockIdx.x * blockDim.x + threadIdx.x;
    if (idx >= DD * DD) return;
    int h = idx >> 11;
    int d = (idx >> 4) & 127;
    int k = idx & 15;
    g_wt[d * DD + h * DHH + k] = wfc[idx];
}

// ---------------- fp16 helpers ----------------
__device__ __forceinline__ uint32_t f2h2(float lo, float hi) {
    __half2 h = __floats2half2_rn(lo, hi);
    return *(uint32_t*)&h;
}
__device__ __forceinline__ void mma_f16(float* c, const uint32_t* a, const uint32_t* b) {
    asm volatile(
        "mma.sync.aligned.m16n8k16.row.col.f32.f16.f16.f32 "
        "{%0,%1,%2,%3}, {%4,%5,%6,%7}, {%8,%9}, {%0,%1,%2,%3};"
        : "+f"(c[0]), "+f"(c[1]), "+f"(c[2]), "+f"(c[3])
        : "r"(a[0]), "r"(a[1]), "r"(a[2]), "r"(a[3]), "r"(b[0]), "r"(b[1]));
}

// Fragment-ordered smem layouts (half2 words; 2 k16-groups per 32-k chunk)
#define A_G_STRIDE 1028   // 8 m-tiles * 32 lanes * 4 words + 4 pad
#define B_U_STRIDE 66     // 32 lanes * 2 words + 2 pad

// ---------------- fp16 tensor-core GEMM, 128x128 tile, 256 threads ----------------
// C[M,Nn] = A[M,K] @ B[K,Nn]; Nn multiple of 128, K multiple of 32.
// 8 warps (2 M x 4 N), warp tile 64x32, mma m16n8k16.
// EPI: 0 = plain store, 1 = relu(acc + bias), 2 = acc + bias + res
template <int EPI>
__global__ void __launch_bounds__(256, 2) tgemm_kernel(
    const float* __restrict__ A, const float* __restrict__ B, float* __restrict__ C,
    int M, int Nn, int K, const float* __restrict__ bias, const float* __restrict__ res)
{
    __shared__ uint32_t Af[2 * A_G_STRIDE];       // 2 k16-groups
    __shared__ uint32_t Bf[2 * 16 * B_U_STRIDE];  // 2 k16-groups x 16 n8-groups

    const int tid = threadIdx.x;
    const int lane = tid & 31;
    const int wid = tid >> 5;
    const int wm = wid >> 2;      // 0..1
    const int wn = wid & 3;       // 0..3
    const int m0 = blockIdx.x * 128;
    const int n0 = blockIdx.y * 128;

    // loader coords
    const int a_m = tid >> 3;            // 0..31 base row (stride 32 via it)
    const int a_kq = tid & 7;            // float4 k-quad (k = 4q..4q+3)
    const int b_kp = tid >> 5;           // 0..7: k rows 2*b_kp(+1), +16
    const int b_nq = tid & 31;           // float4 n-quad

    uint32_t aw[8];   // staged A half2 words
    uint32_t bw[8];   // staged B half2 words

    auto ldg_chunk = [&](int k0) {
        // A: 4 rows per thread (a_m + 32*it), 1 float4 each -> 2 half2 words
#pragma unroll
        for (int it = 0; it < 4; ++it) {
            int ml = a_m + it * 32;
            float4 v = make_float4(0.f, 0.f, 0.f, 0.f);
            if (m0 + ml < M) v = *(const float4*)&A[(size_t)(m0 + ml) * K + k0 + a_kq * 4];
            aw[it * 2 + 0] = f2h2(v.x, v.y);
            aw[it * 2 + 1] = f2h2(v.z, v.w);
        }
        // B: two (k,k+1) row pairs at n-quad -> 4 half2 words each
#pragma unroll
        for (int s = 0; s < 2; ++s) {
            int kk = 2 * b_kp + 16 * s;
            float4 v0 = *(const float4*)&B[(size_t)(k0 + kk) * Nn + n0 + b_nq * 4];
            float4 v1 = *(const float4*)&B[(size_t)(k0 + kk + 1) * Nn + n0 + b_nq * 4];
            bw[s * 4 + 0] = f2h2(v0.x, v1.x);
            bw[s * 4 + 1] = f2h2(v0.y, v1.y);
            bw[s * 4 + 2] = f2h2(v0.z, v1.z);
            bw[s * 4 + 3] = f2h2(v0.w, v1.w);
        }
    };

    auto sts_chunk = [&]() {
        // A words: word (m, pair p): g=p>>3, pl=p&7, t=m>>4, mr=m&15,
        //   lw=(mr&7)*4+(pl&3), iw=(mr>>3)+2*(pl>>2)
#pragma unroll
        for (int it = 0; it < 4; ++it) {
            int ml = a_m + it * 32;
            int t = ml >> 4;
            int mr = ml & 15;
#pragma unroll
            for (int j = 0; j < 2; ++j) {
                int p = 2 * a_kq + j;            // pair index 0..15
                int g = p >> 3, pl = p & 7;
                int lw = (mr & 7) * 4 + (pl & 3);
                int iw = (mr >> 3) + 2 * (pl >> 2);
                Af[g * A_G_STRIDE + t * 128 + lw * 4 + iw] = aw[it * 2 + j];
            }
        }
        // B words: word (n, pair p): u=n>>3, nl=n&7, lw=nl*4+(pl&3), iw=pl>>2
#pragma unroll
        for (int s = 0; s < 2; ++s) {
            int g = s;                           // pair = b_kp + 8s -> group s
            int pl = b_kp;
#pragma unroll
            for (int j = 0; j < 4; ++j) {
                int n = 4 * b_nq + j;
                int u = n >> 3, nl = n & 7;
                int lw = nl * 4 + (pl & 3);
                int iw = pl >> 2;
                Bf[(g * 16 + u) * B_U_STRIDE + lw * 2 + iw] = bw[s * 4 + j];
            }
        }
    };

    float acc[4][4][4];
#pragma unroll
    for (int i = 0; i < 4; ++i)
#pragma unroll
        for (int j = 0; j < 4; ++j)
#pragma unroll
            for (int r = 0; r < 4; ++r) acc[i][j][r] = 0.f;

    auto mma_chunk = [&]() {
#pragma unroll
        for (int g = 0; g < 2; ++g) {
            uint32_t af[4][4], bf[4][2];
#pragma unroll
            for (int mt = 0; mt < 4; ++mt)
                *(uint4*)af[mt] = *(const uint4*)&Af[g * A_G_STRIDE + (wm * 4 + mt) * 128 + lane * 4];
#pragma unroll
            for (int nt = 0; nt < 4; ++nt)
                *(uint2*)bf[nt] = *(const uint2*)&Bf[(g * 16 + wn * 4 + nt) * B_U_STRIDE + lane * 2];
#pragma unroll
            for (int mt = 0; mt < 4; ++mt)
#pragma unroll
                for (int nt = 0; nt < 4; ++nt)
                    mma_f16(acc[mt][nt], af[mt], bf[nt]);
        }
    };

    const int CHUNKS = K >> 5;
    ldg_chunk(0);
    sts_chunk();
    __syncthreads();
    for (int c = 1; c < CHUNKS; ++c) {
        ldg_chunk(c * 32);
        mma_chunk();
        __syncthreads();
        sts_chunk();
        __syncthreads();
    }
    mma_chunk();

    // epilogue (C frag layout: c0..c3 = (lr,2lc),(lr,2lc+1),(lr+8,2lc),(lr+8,2lc+1))
    const int lr = lane >> 2;
    const int lc = lane & 3;
#pragma unroll
    for (int mt = 0; mt < 4; ++mt) {
#pragma unroll
        for (int nt = 0; nt < 4; ++nt) {
            int row = m0 + wm * 64 + mt * 16 + lr;
            int col = n0 + wn * 32 + nt * 8 + 2 * lc;
            float c0 = acc[mt][nt][0], c1 = acc[mt][nt][1];
            float c2 = acc[mt][nt][2], c3 = acc[mt][nt][3];
            if (EPI == 1) {
                float b0 = bias[col], b1 = bias[col + 1];
                c0 = fmaxf(c0 + b0, 0.f); c1 = fmaxf(c1 + b1, 0.f);
                c2 = fmaxf(c2 + b0, 0.f); c3 = fmaxf(c3 + b1, 0.f);
            }
            if (EPI == 2) {
                float b0 = bias[col], b1 = bias[col + 1];
                if (row < M) {
                    c0 += b0 + res[(size_t)row * Nn + col];
                    c1 += b1 + res[(size_t)row * Nn + col + 1];
                }
                if (row + 8 < M) {
                    c2 += b0 + res[(size_t)(row + 8) * Nn + col];
                    c3 += b1 + res[(size_t)(row + 8) * Nn + col + 1];
                }
            }
            if (row < M)     *(float2*)&C[(size_t)row * Nn + col]       = make_float2(c0, c1);
            if (row + 8 < M) *(float2*)&C[(size_t)(row + 8) * Nn + col] = make_float2(c2, c3);
        }
    }
}

// ---------------- el / er: one thread per (node, head) ----------------
__global__ void eler_kernel(const float* __restrict__ a_l, const float* __restrict__ a_r) {
    int idx = blockIdx.x * blockDim.x + threadIdx.x;
    if (idx >= NN * HH) return;
    int n = idx >> 3;
    int h = idx & 7;
    const float4* zp = (const float4*)&g_z[n * DD + h * DHH];
    const float4* lp = (const float4*)&a_l[h * DHH];
    const float4* rp = (const float4*)&a_r[h * DHH];
    float pl = 0.f, pr = 0.f;
#pragma unroll
    for (int q = 0; q < 4; ++q) {
        float4 z = zp[q], l = lp[q], r = rp[q];
        pl += z.x * l.x + z.y * l.y + z.z * l.z + z.w * l.w;
        pr += z.x * r.x + z.y * r.y + z.z * r.z + z.w * r.w;
    }
    g_el[idx] = pl;
    g_er[idx] = pr;
}

// ---------------- degree histogram ----------------
__global__ void deg_kernel(const int* __restrict__ edst) {
    int e = blockIdx.x * blockDim.x + threadIdx.x;
    if (e >= EE) return;
    atomicAdd(&g_deg[edst[e]], 1);
}

// ---------------- exclusive scan over deg ----------------
__global__ void scan1_kernel() {
    __shared__ int sh[256];
    int t = threadIdx.x;
    int i = blockIdx.x * 256 + t;
    int v = (i < NN) ? g_deg[i] : 0;
    sh[t] = v;
    __syncthreads();
#pragma unroll
    for (int off = 1; off < 256; off <<= 1) {
        int x = (t >= off) ? sh[t - off] : 0;
        __syncthreads();
        sh[t] += x;
        __syncthreads();
    }
    if (i < NN) g_base[i] = sh[t] - v;
    if (t == 255) g_bsum[blockIdx.x] = sh[255];
}
__global__ void scan2_kernel() {
    __shared__ int sh[256];
    int t = threadIdx.x;
    int v = (t < NBLK_SCAN) ? g_bsum[t] : 0;
    sh[t] = v;
    __syncthreads();
#pragma unroll
    for (int off = 1; off < 256; off <<= 1) {
        int x = (t >= off) ? sh[t - off] : 0;
        __syncthreads();
        sh[t] += x;
        __syncthreads();
    }
    g_boff[t] = sh[t] - v;
}
__global__ void scan3_kernel() {
    int i = blockIdx.x * blockDim.x + threadIdx.x;
    if (i < NN) g_base[i] += g_boff[i >> 8];
}

// ---------------- scatter edges into CSR slots + compute head weights ----------------
__global__ void scatter_kernel(const int* __restrict__ esrc, const int* __restrict__ edst) {
    int e = blockIdx.x * blockDim.x + threadIdx.x;
    if (e >= EE) return;
    int s = esrc[e], d = edst[e];
    int pos = g_base[d] + atomicAdd(&g_cursor[d], 1);
    g_srcs[pos] = s;
    float4 el0 = *(const float4*)&g_el[s * HH];
    float4 el1 = *(const float4*)&g_el[s * HH + 4];
    float4 er0 = *(const float4*)&g_er[d * HH];
    float4 er1 = *(const float4*)&g_er[d * HH + 4];
    float ev[8] = {el0.x + er0.x, el0.y + er0.y, el0.z + er0.z, el0.w + er0.w,
                   el1.x + er1.x, el1.y + er1.y, el1.z + er1.z, el1.w + er1.w};
    float w[8];
#pragma unroll
    for (int h = 0; h < 8; ++h) {
        float v = ev[h];
        v = (v > 0.f) ? v : 0.01f * v;
        w[h] = __expf(v);
    }
    *(float4*)&g_ws[(size_t)pos * HH]     = make_float4(w[0], w[1], w[2], w[3]);
    *(float4*)&g_ws[(size_t)pos * HH + 4] = make_float4(w[4], w[5], w[6], w[7]);
}

// ---------------- warp-per-node aggregation (no atomics) ----------------
__global__ void __launch_bounds__(256) agg_kernel() {
    int n = blockIdx.x * 8 + (threadIdx.x >> 5);
    int lane = threadIdx.x & 31;
    if (n >= NN) return;
    int start = g_base[n];
    int deg = g_deg[n];
    float4 acc = make_float4(0.f, 0.f, 0.f, 0.f);
    if (deg > 0) {
        float s0 = 0.f, s1 = 0.f, s2 = 0.f, s3 = 0.f;
        float s4 = 0.f, s5 = 0.f, s6 = 0.f, s7 = 0.f;
        for (int i = start + lane; i < start + deg; i += 32) {
            float4 wa = *(const float4*)&g_ws[(size_t)i * HH];
            float4 wb = *(const float4*)&g_ws[(size_t)i * HH + 4];
            s0 += wa.x; s1 += wa.y; s2 += wa.z; s3 += wa.w;
            s4 += wb.x; s5 += wb.y; s6 += wb.z; s7 += wb.w;
        }
#pragma unroll
        for (int o = 16; o >= 1; o >>= 1) {
            s0 += __shfl_xor_sync(0xffffffffu, s0, o);
            s1 += __shfl_xor_sync(0xffffffffu, s1, o);
            s2 += __shfl_xor_sync(0xffffffffu, s2, o);
            s3 += __shfl_xor_sync(0xffffffffu, s3, o);
            s4 += __shfl_xor_sync(0xffffffffu, s4, o);
            s5 += __shfl_xor_sync(0xffffffffu, s5, o);
            s6 += __shfl_xor_sync(0xffffffffu, s6, o);
            s7 += __shfl_xor_sync(0xffffffffu, s7, o);
        }
        int h = lane >> 2;
        float sv;
        switch (h) {
            case 0: sv = s0; break;
            case 1: sv = s1; break;
            case 2: sv = s2; break;
            case 3: sv = s3; break;
            case 4: sv = s4; break;
            case 5: sv = s5; break;
            case 6: sv = s6; break;
            default: sv = s7; break;
        }
        float inv = 1.f / fmaxf(sv, 1e-9f);
        for (int i = start; i < start + deg; ++i) {
            int src = g_srcs[i];
            float alpha = g_ws[(size_t)i * HH + h] * inv;
            float4 zv = *(const float4*)&g_z[(size_t)src * DD + lane * 4];
            acc.x = fmaf(alpha, zv.x, acc.x);
            acc.y = fmaf(alpha, zv.y, acc.y);
            acc.z = fmaf(alpha, zv.z, acc.z);
            acc.w = fmaf(alpha, zv.w, acc.w);
        }
    }
    *(float4*)&g_hagg[(size_t)n * DD + lane * 4] = acc;
}

// ---------------- elu + residual + LayerNorm (warp per node) ----------------
__global__ void ln_kernel(const float* __restrict__ x,
                          const float* __restrict__ gamma, const float* __restrict__ beta) {
    int warp = threadIdx.x >> 5;
    int lane = threadIdx.x & 31;
    int n = blockIdx.x * 8 + warp;
    if (n >= NN) return;
    float4 hv = ((const float4*)(g_hagg + n * DD))[lane];
    float4 xv = ((const float4*)(x + n * DD))[lane];
    float4 r;
    r.x = xv.x + (hv.x > 0.f ? hv.x : expm1f(hv.x));
    r.y = xv.y + (hv.y > 0.f ? hv.y : expm1f(hv.y));
    r.z = xv.z + (hv.z > 0.f ? hv.z : expm1f(hv.z));
    r.w = xv.w + (hv.w > 0.f ? hv.w : expm1f(hv.w));
    ((float4*)(g_hres + n * DD))[lane] = r;
    float sum = r.x + r.y + r.z + r.w;
    float sq = r.x * r.x + r.y * r.y + r.z * r.z + r.w * r.w;
#pragma unroll
    for (int o = 16; o >= 1; o >>= 1) {
        sum += __shfl_xor_sync(0xffffffffu, sum, o);
        sq  += __shfl_xor_sync(0xffffffffu, sq, o);
    }
    float mu = sum * (1.f / 128.f);
    float var = sq * (1.f / 128.f) - mu * mu;
    float rstd = rsqrtf(var + 1e-5f);
    float4 gv = ((const float4*)gamma)[lane];
    float4 bv = ((const float4*)beta)[lane];
    float4 o;
    o.x = (r.x - mu) * rstd * gv.x + bv.x;
    o.y = (r.y - mu) * rstd * gv.y + bv.y;
    o.z = (r.z - mu) * rstd * gv.z + bv.z;
    o.w = (r.w - mu) * rstd * gv.w + bv.w;
    ((float4*)(g_ln + n * DD))[lane] = o;
}

// ---------------- launch ----------------
extern "C" void kernel_launch(void* const* d_in, const int* in_sizes, int n_in,
                              void* d_out, int out_size) {
    const float* x      = (const float*)d_in[0];
    const float* wfc    = (const float*)d_in[1];
    const float* a_l    = (const float*)d_in[2];
    const float* a_r    = (const float*)d_in[3];
    const float* gamma  = (const float*)d_in[4];
    const float* beta   = (const float*)d_in[5];
    const float* W1     = (const float*)d_in[6];
    const float* b1     = (const float*)d_in[7];
    const float* W2     = (const float*)d_in[8];
    const float* b2     = (const float*)d_in[9];
    const int* esrc     = (const int*)d_in[10];
    const int* edst     = (const int*)d_in[11];
    float* out          = (float*)d_out;

    float *p_z, *p_wt, *p_ln, *p_inter, *p_hres;
    cudaGetSymbolAddress((void**)&p_z, g_z);
    cudaGetSymbolAddress((void**)&p_wt, g_wt);
    cudaGetSymbolAddress((void**)&p_ln, g_ln);
    cudaGetSymbolAddress((void**)&p_inter, g_inter);
    cudaGetSymbolAddress((void**)&p_hres, g_hres);

    // launch order: slot 4 (1-indexed) = tgemm so ncu profiles the GEMM
    zero_kernel<<<(NN + 255) / 256, 256>>>();
    transpose_wfc<<<(DD * DD + 255) / 256, 256>>>(wfc);
    deg_kernel<<<(EE + 255) / 256, 256>>>(edst);

    // z = x @ WT
    {
        dim3 grid((NN + 127) / 128, 1);
        tgemm_kernel<0><<<grid, 256>>>(x, p_wt, p_z, NN, DD, DD, nullptr, nullptr);
    }
    eler_kernel<<<(NN * HH + 255) / 256, 256>>>(a_l, a_r);

    scan1_kernel<<<NBLK_SCAN, 256>>>();
    scan2_kernel<<<1, 256>>>();
    scan3_kernel<<<(NN + 255) / 256, 256>>>();
    scatter_kernel<<<(EE + 255) / 256, 256>>>(esrc, edst);

    agg_kernel<<<(NN + 7) / 8, 256>>>();
    ln_kernel<<<(NN + 7) / 8, 256>>>(x, gamma, beta);

    // inter = relu(ln @ W1 + b1)
    {
        dim3 grid((NN + 127) / 128, DFF / 128);
        tgemm_kernel<1><<<grid, 256>>>(p_ln, W1, p_inter, NN, DFF, DD, b1, nullptr);
    }
    // out = inter @ W2 + b2 + hres
    {
        dim3 grid((NN + 127) / 128, 1);
        tgemm_kernel<2><<<grid, 256>>>(p_inter, W2, out, NN, DD, DFF, b2, p_hres);
    }
}

// round 9
// speedup vs baseline: 1.6071x; 1.1606x over previous
#include <cuda_runtime.h>
#include <cuda_fp16.h>
#include <math.h>
#include <stdint.h>

#define NN 50000
#define DD 128
#define HH 8
#define DHH 16
#define EE 800000
#define DFF 512
#define NBLK_SCAN 196   // ceil(50000/256)

// ---------------- scratch (static device globals; no allocation) ----------------
__device__ __half    g_zh[NN * DD];        // z, half
__device__ __half    g_lnh[NN * DD];       // layernorm out, half
__device__ __half    g_interh[NN * DFF];   // FFN intermediate, half
__device__ uint32_t  g_wtp[64 * DD];       // W_fc^T paired half2 (k,k+1)
__device__ uint32_t  g_w1p[64 * DFF];      // W1 paired
__device__ uint32_t  g_w2p[256 * DD];      // W2 paired
__device__ float g_el[NN * HH];
__device__ float g_er[NN * HH];
__device__ float g_ws[EE * HH];
__device__ int   g_srcs[EE];
__device__ int   g_deg[NN];
__device__ int   g_cursor[NN];
__device__ int   g_base[NN];
__device__ int   g_bsum[256];
__device__ int   g_boff[256];
__device__ float g_hagg[NN * DD];
__device__ float g_hres[NN * DD];

__device__ __forceinline__ uint32_t f2h2(float lo, float hi) {
    __half2 h = __floats2half2_rn(lo, hi);
    return *(uint32_t*)&h;
}

// ---------------- zero init (counters only) ----------------
__global__ void zero_kernel() {
    int i = blockIdx.x * blockDim.x + threadIdx.x;
    if (i < NN) { g_deg[i] = 0; g_cursor[i] = 0; }
}

// ---------------- W_fc -> paired half2 [dp][h*16+k] ----------------
__global__ void transpose_wfc_pair(const float* __restrict__ wfc) {
    int idx = blockIdx.x * blockDim.x + threadIdx.x;
    if (idx >= 64 * DD) return;
    int dp = idx >> 7;
    int col = idx & 127;
    int h = col >> 4;
    int k = col & 15;
    float v0 = wfc[h * 2048 + (2 * dp) * 16 + k];
    float v1 = wfc[h * 2048 + (2 * dp + 1) * 16 + k];
    g_wtp[idx] = f2h2(v0, v1);
}

// ---------------- generic weight pairing: out[kp*N+n] = half2(W[2kp][n], W[2kp+1][n]) --
__global__ void pair_w(const float* __restrict__ W, uint32_t* __restrict__ out,
                       int N, int logN, int total) {
    int idx = blockIdx.x * blockDim.x + threadIdx.x;
    if (idx >= total) return;
    int n = idx & (N - 1);
    int kp = idx >> logN;
    out[idx] = f2h2(W[(size_t)(2 * kp) * N + n], W[(size_t)(2 * kp + 1) * N + n]);
}

// ---------------- fp16 mma ----------------
__device__ __forceinline__ void mma_f16(float* c, const uint32_t* a, const uint32_t* b) {
    asm volatile(
        "mma.sync.aligned.m16n8k16.row.col.f32.f16.f16.f32 "
        "{%0,%1,%2,%3}, {%4,%5,%6,%7}, {%8,%9}, {%0,%1,%2,%3};"
        : "+f"(c[0]), "+f"(c[1]), "+f"(c[2]), "+f"(c[3])
        : "r"(a[0]), "r"(a[1]), "r"(a[2]), "r"(a[3]), "r"(b[0]), "r"(b[1]));
}

#define A_G_STRIDE 1028
#define B_U_STRIDE 66

// ---------------- fp16 tensor GEMM, 128x128 tile, 256 threads ----------------
// B is PRE-PAIRED half2 [K/2, Nn] uint32. A: f32 row-major (AHALF=0) or half (AHALF=1).
// C: half (CHALF=1) or float. EPI: 0 plain, 1 relu+bias, 2 bias+res (float C).
template <int EPI, int AHALF, int CHALF>
__global__ void __launch_bounds__(256, 2) tgemm_kernel(
    const void* __restrict__ Av, const uint32_t* __restrict__ Bp, void* __restrict__ Cv,
    int M, int Nn, int K, const float* __restrict__ bias, const float* __restrict__ res)
{
    __shared__ uint32_t Af[2 * A_G_STRIDE];
    __shared__ uint32_t Bf[2 * 16 * B_U_STRIDE];

    const float* A32 = (const float*)Av;
    const __half* A16 = (const __half*)Av;
    float* Cf = (float*)Cv;
    __half* Ch = (__half*)Cv;

    const int tid = threadIdx.x;
    const int lane = tid & 31;
    const int wid = tid >> 5;
    const int wm = wid >> 2;
    const int wn = wid & 3;
    const int m0 = blockIdx.x * 128;
    const int n0 = blockIdx.y * 128;

    // A f32 loader coords
    const int a_m = tid >> 3;
    const int a_kq = tid & 7;
    // A half loader coords
    const int ah_m = tid >> 2;     // 0..63
    const int ah_q = tid & 3;      // k-octet
    // B loader coords
    const int b_p = tid >> 5;      // 0..7
    const int b_nq = tid & 31;

    uint32_t aw[8];
    uint4 avh[2];
    uint4 bv[2];

    auto ldg_chunk = [&](int k0) {
        if constexpr (AHALF) {
#pragma unroll
            for (int it = 0; it < 2; ++it) {
                int m = ah_m + it * 64;
                avh[it] = make_uint4(0, 0, 0, 0);
                if (m0 + m < M) avh[it] = *(const uint4*)&A16[(size_t)(m0 + m) * K + k0 + ah_q * 8];
            }
        } else {
#pragma unroll
            for (int it = 0; it < 4; ++it) {
                int ml = a_m + it * 32;
                float4 v = make_float4(0.f, 0.f, 0.f, 0.f);
                if (m0 + ml < M) v = *(const float4*)&A32[(size_t)(m0 + ml) * K + k0 + a_kq * 4];
                aw[it * 2 + 0] = f2h2(v.x, v.y);
                aw[it * 2 + 1] = f2h2(v.z, v.w);
            }
        }
        const int kp0 = k0 >> 1;
#pragma unroll
        for (int it = 0; it < 2; ++it) {
            int p = b_p + 8 * it;
            bv[it] = *(const uint4*)&Bp[(size_t)(kp0 + p) * Nn + n0 + b_nq * 4];
        }
    };

    auto sts_chunk = [&]() {
        if constexpr (AHALF) {
#pragma unroll
            for (int it = 0; it < 2; ++it) {
                int m = ah_m + it * 64;
                int t4 = m >> 4;
                int mr = m & 15;
                const uint32_t* w = (const uint32_t*)&avh[it];
#pragma unroll
                for (int j = 0; j < 4; ++j) {
                    int p = 4 * ah_q + j;
                    int g = p >> 3, pl = p & 7;
                    int lw = (mr & 7) * 4 + (pl & 3);
                    int iw = (mr >> 3) + 2 * (pl >> 2);
                    Af[g * A_G_STRIDE + t4 * 128 + lw * 4 + iw] = w[j];
                }
            }
        } else {
#pragma unroll
            for (int it = 0; it < 4; ++it) {
                int ml = a_m + it * 32;
                int t4 = ml >> 4;
                int mr = ml & 15;
#pragma unroll
                for (int j = 0; j < 2; ++j) {
                    int p = 2 * a_kq + j;
                    int g = p >> 3, pl = p & 7;
                    int lw = (mr & 7) * 4 + (pl & 3);
                    int iw = (mr >> 3) + 2 * (pl >> 2);
                    Af[g * A_G_STRIDE + t4 * 128 + lw * 4 + iw] = aw[it * 2 + j];
                }
            }
        }
#pragma unroll
        for (int it = 0; it < 2; ++it) {
            int p = b_p + 8 * it;
            int g = p >> 3, pl = p & 7;
            const uint32_t* w = (const uint32_t*)&bv[it];
#pragma unroll
            for (int j = 0; j < 4; ++j) {
                int n = 4 * b_nq + j;
                int u = n >> 3, nl = n & 7;
                int lw = nl * 4 + (pl & 3);
                int iw = pl >> 2;
                Bf[(g * 16 + u) * B_U_STRIDE + lw * 2 + iw] = w[j];
            }
        }
    };

    float acc[4][4][4];
#pragma unroll
    for (int i = 0; i < 4; ++i)
#pragma unroll
        for (int j = 0; j < 4; ++j)
#pragma unroll
            for (int r = 0; r < 4; ++r) acc[i][j][r] = 0.f;

    auto mma_chunk = [&]() {
#pragma unroll
        for (int g = 0; g < 2; ++g) {
            uint32_t af[4][4], bf[4][2];
#pragma unroll
            for (int mt = 0; mt < 4; ++mt)
                *(uint4*)af[mt] = *(const uint4*)&Af[g * A_G_STRIDE + (wm * 4 + mt) * 128 + lane * 4];
#pragma unroll
            for (int nt = 0; nt < 4; ++nt)
                *(uint2*)bf[nt] = *(const uint2*)&Bf[(g * 16 + wn * 4 + nt) * B_U_STRIDE + lane * 2];
#pragma unroll
            for (int mt = 0; mt < 4; ++mt)
#pragma unroll
                for (int nt = 0; nt < 4; ++nt)
                    mma_f16(acc[mt][nt], af[mt], bf[nt]);
        }
    };

    const int CHUNKS = K >> 5;
    ldg_chunk(0);
    sts_chunk();
    __syncthreads();
    for (int c = 1; c < CHUNKS; ++c) {
        ldg_chunk(c * 32);
        mma_chunk();
        __syncthreads();
        sts_chunk();
        __syncthreads();
    }
    mma_chunk();

    // epilogue
    const int lr = lane >> 2;
    const int lc = lane & 3;
#pragma unroll
    for (int mt = 0; mt < 4; ++mt) {
#pragma unroll
        for (int nt = 0; nt < 4; ++nt) {
            int row = m0 + wm * 64 + mt * 16 + lr;
            int col = n0 + wn * 32 + nt * 8 + 2 * lc;
            float c0 = acc[mt][nt][0], c1 = acc[mt][nt][1];
            float c2 = acc[mt][nt][2], c3 = acc[mt][nt][3];
            if (EPI == 1) {
                float b0 = bias[col], b1 = bias[col + 1];
                c0 = fmaxf(c0 + b0, 0.f); c1 = fmaxf(c1 + b1, 0.f);
                c2 = fmaxf(c2 + b0, 0.f); c3 = fmaxf(c3 + b1, 0.f);
            }
            if (EPI == 2) {
                float b0 = bias[col], b1 = bias[col + 1];
                if (row < M) {
                    c0 += b0 + res[(size_t)row * Nn + col];
                    c1 += b1 + res[(size_t)row * Nn + col + 1];
                }
                if (row + 8 < M) {
                    c2 += b0 + res[(size_t)(row + 8) * Nn + col];
                    c3 += b1 + res[(size_t)(row + 8) * Nn + col + 1];
                }
            }
            if (CHALF) {
                if (row < M)     *(uint32_t*)&Ch[(size_t)row * Nn + col]       = f2h2(c0, c1);
                if (row + 8 < M) *(uint32_t*)&Ch[(size_t)(row + 8) * Nn + col] = f2h2(c2, c3);
            } else {
                if (row < M)     *(float2*)&Cf[(size_t)row * Nn + col]       = make_float2(c0, c1);
                if (row + 8 < M) *(float2*)&Cf[(size_t)(row + 8) * Nn + col] = make_float2(c2, c3);
            }
        }
    }
}

// ---------------- el / er: one thread per (node, head), z half ----------------
__global__ void eler_kernel(const float* __restrict__ a_l, const float* __restrict__ a_r) {
    int idx = blockIdx.x * blockDim.x + threadIdx.x;
    if (idx >= NN * HH) return;
    int n = idx >> 3;
    int h = idx & 7;
    const uint32_t* zw = (const uint32_t*)&g_zh[n * DD + h * DHH];
    uint4 z0 = *(const uint4*)zw;
    uint4 z1 = *(const uint4*)(zw + 4);
    uint32_t w[8] = {z0.x, z0.y, z0.z, z0.w, z1.x, z1.y, z1.z, z1.w};
    const float* lp = &a_l[h * DHH];
    const float* rp = &a_r[h * DHH];
    float pl = 0.f, pr = 0.f;
#pragma unroll
    for (int q = 0; q < 8; ++q) {
        float2 f = __half22float2(*(__half2*)&w[q]);
        pl += f.x * lp[2 * q] + f.y * lp[2 * q + 1];
        pr += f.x * rp[2 * q] + f.y * rp[2 * q + 1];
    }
    g_el[idx] = pl;
    g_er[idx] = pr;
}

// ---------------- degree histogram ----------------
__global__ void deg_kernel(const int* __restrict__ edst) {
    int e = blockIdx.x * blockDim.x + threadIdx.x;
    if (e >= EE) return;
    atomicAdd(&g_deg[edst[e]], 1);
}

// ---------------- exclusive scan over deg ----------------
__global__ void scan1_kernel() {
    __shared__ int sh[256];
    int t = threadIdx.x;
    int i = blockIdx.x * 256 + t;
    int v = (i < NN) ? g_deg[i] : 0;
    sh[t] = v;
    __syncthreads();
#pragma unroll
    for (int off = 1; off < 256; off <<= 1) {
        int x = (t >= off) ? sh[t - off] : 0;
        __syncthreads();
        sh[t] += x;
        __syncthreads();
    }
    if (i < NN) g_base[i] = sh[t] - v;
    if (t == 255) g_bsum[blockIdx.x] = sh[255];
}
__global__ void scan2_kernel() {
    __shared__ int sh[256];
    int t = threadIdx.x;
    int v = (t < NBLK_SCAN) ? g_bsum[t] : 0;
    sh[t] = v;
    __syncthreads();
#pragma unroll
    for (int off = 1; off < 256; off <<= 1) {
        int x = (t >= off) ? sh[t - off] : 0;
        __syncthreads();
        sh[t] += x;
        __syncthreads();
    }
    g_boff[t] = sh[t] - v;
}
__global__ void scan3_kernel() {
    int i = blockIdx.x * blockDim.x + threadIdx.x;
    if (i < NN) g_base[i] += g_boff[i >> 8];
}

// ---------------- scatter edges into CSR slots + compute head weights ----------------
__global__ void scatter_kernel(const int* __restrict__ esrc, const int* __restrict__ edst) {
    int e = blockIdx.x * blockDim.x + threadIdx.x;
    if (e >= EE) return;
    int s = esrc[e], d = edst[e];
    int pos = g_base[d] + atomicAdd(&g_cursor[d], 1);
    g_srcs[pos] = s;
    float4 el0 = *(const float4*)&g_el[s * HH];
    float4 el1 = *(const float4*)&g_el[s * HH + 4];
    float4 er0 = *(const float4*)&g_er[d * HH];
    float4 er1 = *(const float4*)&g_er[d * HH + 4];
    float ev[8] = {el0.x + er0.x, el0.y + er0.y, el0.z + er0.z, el0.w + er0.w,
                   el1.x + er1.x, el1.y + er1.y, el1.z + er1.z, el1.w + er1.w};
    float w[8];
#pragma unroll
    for (int h = 0; h < 8; ++h) {
        float v = ev[h];
        v = (v > 0.f) ? v : 0.01f * v;
        w[h] = __expf(v);
    }
    *(float4*)&g_ws[(size_t)pos * HH]     = make_float4(w[0], w[1], w[2], w[3]);
    *(float4*)&g_ws[(size_t)pos * HH + 4] = make_float4(w[4], w[5], w[6], w[7]);
}

// ---------------- warp-per-node aggregation (no atomics, z half) ----------------
__global__ void __launch_bounds__(256) agg_kernel() {
    int n = blockIdx.x * 8 + (threadIdx.x >> 5);
    int lane = threadIdx.x & 31;
    if (n >= NN) return;
    int start = g_base[n];
    int deg = g_deg[n];
    float4 acc = make_float4(0.f, 0.f, 0.f, 0.f);
    if (deg > 0) {
        float s0 = 0.f, s1 = 0.f, s2 = 0.f, s3 = 0.f;
        float s4 = 0.f, s5 = 0.f, s6 = 0.f, s7 = 0.f;
        for (int i = start + lane; i < start + deg; i += 32) {
            float4 wa = *(const float4*)&g_ws[(size_t)i * HH];
            float4 wb = *(const float4*)&g_ws[(size_t)i * HH + 4];
            s0 += wa.x; s1 += wa.y; s2 += wa.z; s3 += wa.w;
            s4 += wb.x; s5 += wb.y; s6 += wb.z; s7 += wb.w;
        }
#pragma unroll
        for (int o = 16; o >= 1; o >>= 1) {
            s0 += __shfl_xor_sync(0xffffffffu, s0, o);
            s1 += __shfl_xor_sync(0xffffffffu, s1, o);
            s2 += __shfl_xor_sync(0xffffffffu, s2, o);
            s3 += __shfl_xor_sync(0xffffffffu, s3, o);
            s4 += __shfl_xor_sync(0xffffffffu, s4, o);
            s5 += __shfl_xor_sync(0xffffffffu, s5, o);
            s6 += __shfl_xor_sync(0xffffffffu, s6, o);
            s7 += __shfl_xor_sync(0xffffffffu, s7, o);
        }
        int h = lane >> 2;
        float sv;
        switch (h) {
            case 0: sv = s0; break;
            case 1: sv = s1; break;
            case 2: sv = s2; break;
            case 3: sv = s3; break;
            case 4: sv = s4; break;
            case 5: sv = s5; break;
            case 6: sv = s6; break;
            default: sv = s7; break;
        }
        float inv = 1.f / fmaxf(sv, 1e-9f);
        for (int i = start; i < start + deg; ++i) {
            int src = g_srcs[i];
            float alpha = g_ws[(size_t)i * HH + h] * inv;
            uint2 zv = *(const uint2*)&g_zh[(size_t)src * DD + lane * 4];
            float2 p0 = __half22float2(*(__half2*)&zv.x);
            float2 p1 = __half22float2(*(__half2*)&zv.y);
            acc.x = fmaf(alpha, p0.x, acc.x);
            acc.y = fmaf(alpha, p0.y, acc.y);
            acc.z = fmaf(alpha, p1.x, acc.z);
            acc.w = fmaf(alpha, p1.y, acc.w);
        }
    }
    *(float4*)&g_hagg[(size_t)n * DD + lane * 4] = acc;
}

// ---------------- elu + residual + LayerNorm (warp per node); ln out half ----------
__global__ void ln_kernel(const float* __restrict__ x,
                          const float* __restrict__ gamma, const float* __restrict__ beta) {
    int warp = threadIdx.x >> 5;
    int lane = threadIdx.x & 31;
    int n = blockIdx.x * 8 + warp;
    if (n >= NN) return;
    float4 hv = ((const float4*)(g_hagg + n * DD))[lane];
    float4 xv = ((const float4*)(x + n * DD))[lane];
    float4 r;
    r.x = xv.x + (hv.x > 0.f ? hv.x : expm1f(hv.x));
    r.y = xv.y + (hv.y > 0.f ? hv.y : expm1f(hv.y));
    r.z = xv.z + (hv.z > 0.f ? hv.z : expm1f(hv.z));
    r.w = xv.w + (hv.w > 0.f ? hv.w : expm1f(hv.w));
    ((float4*)(g_hres + n * DD))[lane] = r;
    float sum = r.x + r.y + r.z + r.w;
    float sq = r.x * r.x + r.y * r.y + r.z * r.z + r.w * r.w;
#pragma unroll
    for (int o = 16; o >= 1; o >>= 1) {
        sum += __shfl_xor_sync(0xffffffffu, sum, o);
        sq  += __shfl_xor_sync(0xffffffffu, sq, o);
    }
    float mu = sum * (1.f / 128.f);
    float var = sq * (1.f / 128.f) - mu * mu;
    float rstd = rsqrtf(var + 1e-5f);
    float4 gv = ((const float4*)gamma)[lane];
    float4 bv = ((const float4*)beta)[lane];
    float o0 = (r.x - mu) * rstd * gv.x + bv.x;
    float o1 = (r.y - mu) * rstd * gv.y + bv.y;
    float o2 = (r.z - mu) * rstd * gv.z + bv.z;
    float o3 = (r.w - mu) * rstd * gv.w + bv.w;
    uint2 ow;
    ow.x = f2h2(o0, o1);
    ow.y = f2h2(o2, o3);
    *(uint2*)&g_lnh[(size_t)n * DD + lane * 4] = ow;
}

// ---------------- launch ----------------
extern "C" void kernel_launch(void* const* d_in, const int* in_sizes, int n_in,
                              void* d_out, int out_size) {
    const float* x      = (const float*)d_in[0];
    const float* wfc    = (const float*)d_in[1];
    const float* a_l    = (const float*)d_in[2];
    const float* a_r    = (const float*)d_in[3];
    const float* gamma  = (const float*)d_in[4];
    const float* beta   = (const float*)d_in[5];
    const float* W1     = (const float*)d_in[6];
    const float* b1     = (const float*)d_in[7];
    const float* W2     = (const float*)d_in[8];
    const float* b2     = (const float*)d_in[9];
    const int* esrc     = (const int*)d_in[10];
    const int* edst     = (const int*)d_in[11];
    float* out          = (float*)d_out;

    void *p_zh, *p_lnh, *p_interh, *p_wtp, *p_w1p, *p_w2p;
    float* p_hres;
    cudaGetSymbolAddress(&p_zh, g_zh);
    cudaGetSymbolAddress(&p_lnh, g_lnh);
    cudaGetSymbolAddress(&p_interh, g_interh);
    cudaGetSymbolAddress(&p_wtp, g_wtp);
    cudaGetSymbolAddress(&p_w1p, g_w1p);
    cudaGetSymbolAddress(&p_w2p, g_w2p);
    cudaGetSymbolAddress((void**)&p_hres, g_hres);

    // launch order: slot 4 (1-indexed) = tgemm<0> so ncu profiles the GEMM
    zero_kernel<<<(NN + 255) / 256, 256>>>();
    transpose_wfc_pair<<<(64 * DD + 255) / 256, 256>>>(wfc);
    deg_kernel<<<(EE + 255) / 256, 256>>>(edst);

    // z = x @ WT  (A f32, C half)
    {
        dim3 grid((NN + 127) / 128, 1);
        tgemm_kernel<0, 0, 1><<<grid, 256>>>(x, (const uint32_t*)p_wtp, p_zh,
                                             NN, DD, DD, nullptr, nullptr);
    }
    pair_w<<<(64 * DFF + 255) / 256, 256>>>(W1, (uint32_t*)p_w1p, DFF, 9, 64 * DFF);
    pair_w<<<(256 * DD + 255) / 256, 256>>>(W2, (uint32_t*)p_w2p, DD, 7, 256 * DD);
    eler_kernel<<<(NN * HH + 255) / 256, 256>>>(a_l, a_r);

    scan1_kernel<<<NBLK_SCAN, 256>>>();
    scan2_kernel<<<1, 256>>>();
    scan3_kernel<<<(NN + 255) / 256, 256>>>();
    scatter_kernel<<<(EE + 255) / 256, 256>>>(esrc, edst);

    agg_kernel<<<(NN + 7) / 8, 256>>>();
    ln_kernel<<<(NN + 7) / 8, 256>>>(x, gamma, beta);

    // inter = relu(ln @ W1 + b1)  (A half, C half)
    {
        dim3 grid((NN + 127) / 128, DFF / 128);
        tgemm_kernel<1, 1, 1><<<grid, 256>>>(p_lnh, (const uint32_t*)p_w1p, p_interh,
                                             NN, DFF, DD, b1, nullptr);
    }
    // out = inter @ W2 + b2 + hres  (A half, C float)
    {
        dim3 grid((NN + 127) / 128, 1);
        tgemm_kernel<2, 1, 0><<<grid, 256>>>(p_interh, (const uint32_t*)p_w2p, out,
                                             NN, DD, DFF, b2, p_hres);
    }
}

// round 10
// speedup vs baseline: 1.6864x; 1.0493x over previous
#include <cuda_runtime.h>
#include <cuda_fp16.h>
#include <math.h>
#include <stdint.h>

#define NN 50000
#define DD 128
#define HH 8
#define DHH 16
#define EE 800000
#define DFF 512
#define NBLK_SCAN 196   // ceil(50000/256)

// ---------------- scratch (static device globals; no allocation) ----------------
__device__ __half    g_zh[NN * DD];
__device__ __half    g_lnh[NN * DD];
__device__ __half    g_interh[NN * DFF];
__device__ uint32_t  g_wtp[64 * DD];
__device__ uint32_t  g_w1p[64 * DFF];
__device__ uint32_t  g_w2p[256 * DD];
__device__ float g_el[NN * HH];
__device__ float g_er[NN * HH];
__device__ float g_ws[EE * HH];
__device__ int   g_srcs[EE];
__device__ int   g_deg[NN];
__device__ int   g_cursor[NN];
__device__ int   g_base[NN];
__device__ int   g_bsum[256];
__device__ int   g_boff[256];
__device__ float g_hagg[NN * DD];
__device__ float g_hres[NN * DD];

__device__ __forceinline__ uint32_t f2h2(float lo, float hi) {
    __half2 h = __floats2half2_rn(lo, hi);
    return *(uint32_t*)&h;
}

// ---------------- fused prep: zero counters + pair all weights ----------------
__global__ void prep_kernel(const float* __restrict__ wfc,
                            const float* __restrict__ W1,
                            const float* __restrict__ W2) {
    int i = blockIdx.x * blockDim.x + threadIdx.x;
    if (i < NN) { g_deg[i] = 0; g_cursor[i] = 0; }
    if (i < 64 * DD) {
        int dp = i >> 7;
        int col = i & 127;
        int h = col >> 4;
        int k = col & 15;
        float v0 = wfc[h * 2048 + (2 * dp) * 16 + k];
        float v1 = wfc[h * 2048 + (2 * dp + 1) * 16 + k];
        g_wtp[i] = f2h2(v0, v1);
    }
    if (i < 64 * DFF) {
        int n = i & (DFF - 1);
        int kp = i >> 9;
        g_w1p[i] = f2h2(W1[(size_t)(2 * kp) * DFF + n], W1[(size_t)(2 * kp + 1) * DFF + n]);
    }
    if (i < 256 * DD) {
        int n = i & (DD - 1);
        int kp = i >> 7;
        g_w2p[i] = f2h2(W2[(size_t)(2 * kp) * DD + n], W2[(size_t)(2 * kp + 1) * DD + n]);
    }
}

// ---------------- fp16 mma ----------------
__device__ __forceinline__ void mma_f16(float* c, const uint32_t* a, const uint32_t* b) {
    asm volatile(
        "mma.sync.aligned.m16n8k16.row.col.f32.f16.f16.f32 "
        "{%0,%1,%2,%3}, {%4,%5,%6,%7}, {%8,%9}, {%0,%1,%2,%3};"
        : "+f"(c[0]), "+f"(c[1]), "+f"(c[2]), "+f"(c[3])
        : "r"(a[0]), "r"(a[1]), "r"(a[2]), "r"(a[3]), "r"(b[0]), "r"(b[1]));
}

#define A_G_STRIDE 1028
#define B_U_STRIDE 66

// ---------------- fp16 tensor GEMM, 128x128 tile, 256 threads, smem dbuf ---------
// B is PRE-PAIRED half2 [K/2, Nn] uint32. A: f32 (AHALF=0) or half (AHALF=1).
// C: half (CHALF=1) or float. EPI: 0 plain, 1 relu+bias, 2 bias+res.
template <int EPI, int AHALF, int CHALF>
__global__ void __launch_bounds__(256, 2) tgemm_kernel(
    const void* __restrict__ Av, const uint32_t* __restrict__ Bp, void* __restrict__ Cv,
    int M, int Nn, int K, const float* __restrict__ bias, const float* __restrict__ res)
{
    __shared__ uint32_t Af[2][2 * A_G_STRIDE];
    __shared__ uint32_t Bf[2][2 * 16 * B_U_STRIDE];

    const float* A32 = (const float*)Av;
    const __half* A16 = (const __half*)Av;
    float* Cf = (float*)Cv;
    __half* Ch = (__half*)Cv;

    const int tid = threadIdx.x;
    const int lane = tid & 31;
    const int wid = tid >> 5;
    const int wm = wid >> 2;
    const int wn = wid & 3;
    const int m0 = blockIdx.x * 128;
    const int n0 = blockIdx.y * 128;

    const int a_m = tid >> 3;
    const int a_kq = tid & 7;
    const int ah_m = tid >> 2;
    const int ah_q = tid & 3;
    const int b_p = tid >> 5;
    const int b_nq = tid & 31;

    uint32_t aw[8];
    uint4 avh[2];
    uint4 bv[2];

    auto ldg_chunk = [&](int k0) {
        if constexpr (AHALF) {
#pragma unroll
            for (int it = 0; it < 2; ++it) {
                int m = ah_m + it * 64;
                avh[it] = make_uint4(0, 0, 0, 0);
                if (m0 + m < M) avh[it] = *(const uint4*)&A16[(size_t)(m0 + m) * K + k0 + ah_q * 8];
            }
        } else {
#pragma unroll
            for (int it = 0; it < 4; ++it) {
                int ml = a_m + it * 32;
                float4 v = make_float4(0.f, 0.f, 0.f, 0.f);
                if (m0 + ml < M) v = *(const float4*)&A32[(size_t)(m0 + ml) * K + k0 + a_kq * 4];
                aw[it * 2 + 0] = f2h2(v.x, v.y);
                aw[it * 2 + 1] = f2h2(v.z, v.w);
            }
        }
        const int kp0 = k0 >> 1;
#pragma unroll
        for (int it = 0; it < 2; ++it) {
            int p = b_p + 8 * it;
            bv[it] = *(const uint4*)&Bp[(size_t)(kp0 + p) * Nn + n0 + b_nq * 4];
        }
    };

    auto sts_chunk = [&](int buf) {
        if constexpr (AHALF) {
#pragma unroll
            for (int it = 0; it < 2; ++it) {
                int m = ah_m + it * 64;
                int t4 = m >> 4;
                int mr = m & 15;
                const uint32_t* w = (const uint32_t*)&avh[it];
#pragma unroll
                for (int j = 0; j < 4; ++j) {
                    int p = 4 * ah_q + j;
                    int g = p >> 3, pl = p & 7;
                    int lw = (mr & 7) * 4 + (pl & 3);
                    int iw = (mr >> 3) + 2 * (pl >> 2);
                    Af[buf][g * A_G_STRIDE + t4 * 128 + lw * 4 + iw] = w[j];
                }
            }
        } else {
#pragma unroll
            for (int it = 0; it < 4; ++it) {
                int ml = a_m + it * 32;
                int t4 = ml >> 4;
                int mr = ml & 15;
#pragma unroll
                for (int j = 0; j < 2; ++j) {
                    int p = 2 * a_kq + j;
                    int g = p >> 3, pl = p & 7;
                    int lw = (mr & 7) * 4 + (pl & 3);
                    int iw = (mr >> 3) + 2 * (pl >> 2);
                    Af[buf][g * A_G_STRIDE + t4 * 128 + lw * 4 + iw] = aw[it * 2 + j];
                }
            }
        }
#pragma unroll
        for (int it = 0; it < 2; ++it) {
            int p = b_p + 8 * it;
            int g = p >> 3, pl = p & 7;
            const uint32_t* w = (const uint32_t*)&bv[it];
#pragma unroll
            for (int j = 0; j < 4; ++j) {
                int n = 4 * b_nq + j;
                int u = n >> 3, nl = n & 7;
                int lw = nl * 4 + (pl & 3);
                int iw = pl >> 2;
                Bf[buf][(g * 16 + u) * B_U_STRIDE + lw * 2 + iw] = w[j];
            }
        }
    };

    float acc[4][4][4];
#pragma unroll
    for (int i = 0; i < 4; ++i)
#pragma unroll
        for (int j = 0; j < 4; ++j)
#pragma unroll
            for (int r = 0; r < 4; ++r) acc[i][j][r] = 0.f;

    auto mma_chunk = [&](int buf) {
#pragma unroll
        for (int g = 0; g < 2; ++g) {
            uint32_t af[4][4], bf[4][2];
#pragma unroll
            for (int mt = 0; mt < 4; ++mt)
                *(uint4*)af[mt] = *(const uint4*)&Af[buf][g * A_G_STRIDE + (wm * 4 + mt) * 128 + lane * 4];
#pragma unroll
            for (int nt = 0; nt < 4; ++nt)
                *(uint2*)bf[nt] = *(const uint2*)&Bf[buf][(g * 16 + wn * 4 + nt) * B_U_STRIDE + lane * 2];
#pragma unroll
            for (int mt = 0; mt < 4; ++mt)
#pragma unroll
                for (int nt = 0; nt < 4; ++nt)
                    mma_f16(acc[mt][nt], af[mt], bf[nt]);
        }
    };

    const int CHUNKS = K >> 5;
    ldg_chunk(0);
    sts_chunk(0);
    __syncthreads();
    for (int c = 1; c < CHUNKS; ++c) {
        ldg_chunk(c * 32);
        mma_chunk((c - 1) & 1);
        sts_chunk(c & 1);
        __syncthreads();
    }
    mma_chunk((CHUNKS - 1) & 1);

    // epilogue
    const int lr = lane >> 2;
    const int lc = lane & 3;
#pragma unroll
    for (int mt = 0; mt < 4; ++mt) {
#pragma unroll
        for (int nt = 0; nt < 4; ++nt) {
            int row = m0 + wm * 64 + mt * 16 + lr;
            int col = n0 + wn * 32 + nt * 8 + 2 * lc;
            float c0 = acc[mt][nt][0], c1 = acc[mt][nt][1];
            float c2 = acc[mt][nt][2], c3 = acc[mt][nt][3];
            if (EPI == 1) {
                float b0 = bias[col], b1 = bias[col + 1];
                c0 = fmaxf(c0 + b0, 0.f); c1 = fmaxf(c1 + b1, 0.f);
                c2 = fmaxf(c2 + b0, 0.f); c3 = fmaxf(c3 + b1, 0.f);
            }
            if (EPI == 2) {
                float b0 = bias[col], b1 = bias[col + 1];
                if (row < M) {
                    c0 += b0 + res[(size_t)row * Nn + col];
                    c1 += b1 + res[(size_t)row * Nn + col + 1];
                }
                if (row + 8 < M) {
                    c2 += b0 + res[(size_t)(row + 8) * Nn + col];
                    c3 += b1 + res[(size_t)(row + 8) * Nn + col + 1];
                }
            }
            if (CHALF) {
                if (row < M)     *(uint32_t*)&Ch[(size_t)row * Nn + col]       = f2h2(c0, c1);
                if (row + 8 < M) *(uint32_t*)&Ch[(size_t)(row + 8) * Nn + col] = f2h2(c2, c3);
            } else {
                if (row < M)     *(float2*)&Cf[(size_t)row * Nn + col]       = make_float2(c0, c1);
                if (row + 8 < M) *(float2*)&Cf[(size_t)(row + 8) * Nn + col] = make_float2(c2, c3);
            }
        }
    }
}

// ---------------- el / er: one thread per (node, head), z half ----------------
__global__ void eler_kernel(const float* __restrict__ a_l, const float* __restrict__ a_r) {
    int idx = blockIdx.x * blockDim.x + threadIdx.x;
    if (idx >= NN * HH) return;
    int n = idx >> 3;
    int h = idx & 7;
    const uint32_t* zw = (const uint32_t*)&g_zh[n * DD + h * DHH];
    uint4 z0 = *(const uint4*)zw;
    uint4 z1 = *(const uint4*)(zw + 4);
    uint32_t w[8] = {z0.x, z0.y, z0.z, z0.w, z1.x, z1.y, z1.z, z1.w};
    const float* lp = &a_l[h * DHH];
    const float* rp = &a_r[h * DHH];
    float pl = 0.f, pr = 0.f;
#pragma unroll
    for (int q = 0; q < 8; ++q) {
        float2 f = __half22float2(*(__half2*)&w[q]);
        pl += f.x * lp[2 * q] + f.y * lp[2 * q + 1];
        pr += f.x * rp[2 * q] + f.y * rp[2 * q + 1];
    }
    g_el[idx] = pl;
    g_er[idx] = pr;
}

// ---------------- degree histogram ----------------
__global__ void deg_kernel(const int* __restrict__ edst) {
    int e = blockIdx.x * blockDim.x + threadIdx.x;
    if (e >= EE) return;
    atomicAdd(&g_deg[edst[e]], 1);
}

// ---------------- scan (2 kernels; block-offset add folded into scatter) ----------
__global__ void scan1_kernel() {
    __shared__ int sh[256];
    int t = threadIdx.x;
    int i = blockIdx.x * 256 + t;
    int v = (i < NN) ? g_deg[i] : 0;
    sh[t] = v;
    __syncthreads();
#pragma unroll
    for (int off = 1; off < 256; off <<= 1) {
        int x = (t >= off) ? sh[t - off] : 0;
        __syncthreads();
        sh[t] += x;
        __syncthreads();
    }
    if (i < NN) g_base[i] = sh[t] - v;
    if (t == 255) g_bsum[blockIdx.x] = sh[255];
}
__global__ void scan2_kernel() {
    __shared__ int sh[256];
    int t = threadIdx.x;
    int v = (t < NBLK_SCAN) ? g_bsum[t] : 0;
    sh[t] = v;
    __syncthreads();
#pragma unroll
    for (int off = 1; off < 256; off <<= 1) {
        int x = (t >= off) ? sh[t - off] : 0;
        __syncthreads();
        sh[t] += x;
        __syncthreads();
    }
    g_boff[t] = sh[t] - v;
}

// ---------------- scatter edges into CSR slots + compute head weights ----------------
__global__ void scatter_kernel(const int* __restrict__ esrc, const int* __restrict__ edst) {
    int e = blockIdx.x * blockDim.x + threadIdx.x;
    if (e >= EE) return;
    int s = esrc[e], d = edst[e];
    int pos = g_base[d] + g_boff[d >> 8] + atomicAdd(&g_cursor[d], 1);
    g_srcs[pos] = s;
    float4 el0 = *(const float4*)&g_el[s * HH];
    float4 el1 = *(const float4*)&g_el[s * HH + 4];
    float4 er0 = *(const float4*)&g_er[d * HH];
    float4 er1 = *(const float4*)&g_er[d * HH + 4];
    float ev[8] = {el0.x + er0.x, el0.y + er0.y, el0.z + er0.z, el0.w + er0.w,
                   el1.x + er1.x, el1.y + er1.y, el1.z + er1.z, el1.w + er1.w};
    float w[8];
#pragma unroll
    for (int h = 0; h < 8; ++h) {
        float v = ev[h];
        v = (v > 0.f) ? v : 0.01f * v;
        w[h] = __expf(v);
    }
    *(float4*)&g_ws[(size_t)pos * HH]     = make_float4(w[0], w[1], w[2], w[3]);
    *(float4*)&g_ws[(size_t)pos * HH + 4] = make_float4(w[4], w[5], w[6], w[7]);
}

// ---------------- warp-per-node aggregation (no atomics, src prefetch) ----------
__global__ void __launch_bounds__(256) agg_kernel() {
    int n = blockIdx.x * 8 + (threadIdx.x >> 5);
    int lane = threadIdx.x & 31;
    if (n >= NN) return;
    int start = g_base[n] + g_boff[n >> 8];
    int deg = g_deg[n];
    float4 acc = make_float4(0.f, 0.f, 0.f, 0.f);
    if (deg > 0) {
        float s0 = 0.f, s1 = 0.f, s2 = 0.f, s3 = 0.f;
        float s4 = 0.f, s5 = 0.f, s6 = 0.f, s7 = 0.f;
        for (int i = start + lane; i < start + deg; i += 32) {
            float4 wa = *(const float4*)&g_ws[(size_t)i * HH];
            float4 wb = *(const float4*)&g_ws[(size_t)i * HH + 4];
            s0 += wa.x; s1 += wa.y; s2 += wa.z; s3 += wa.w;
            s4 += wb.x; s5 += wb.y; s6 += wb.z; s7 += wb.w;
        }
#pragma unroll
        for (int o = 16; o >= 1; o >>= 1) {
            s0 += __shfl_xor_sync(0xffffffffu, s0, o);
            s1 += __shfl_xor_sync(0xffffffffu, s1, o);
            s2 += __shfl_xor_sync(0xffffffffu, s2, o);
            s3 += __shfl_xor_sync(0xffffffffu, s3, o);
            s4 += __shfl_xor_sync(0xffffffffu, s4, o);
            s5 += __shfl_xor_sync(0xffffffffu, s5, o);
            s6 += __shfl_xor_sync(0xffffffffu, s6, o);
            s7 += __shfl_xor_sync(0xffffffffu, s7, o);
        }
        int h = lane >> 2;
        float sv;
        switch (h) {
            case 0: sv = s0; break;
            case 1: sv = s1; break;
            case 2: sv = s2; break;
            case 3: sv = s3; break;
            case 4: sv = s4; break;
            case 5: sv = s5; break;
            case 6: sv = s6; break;
            default: sv = s7; break;
        }
        float inv = 1.f / fmaxf(sv, 1e-9f);
        // batched: prefetch up to 32 srcs lane-parallel, broadcast via shfl
        for (int b = 0; b < deg; b += 32) {
            int cnt = min(32, deg - b);
            int mysrc = (lane < cnt) ? g_srcs[start + b + lane] : 0;
#pragma unroll 4
            for (int j = 0; j < cnt; ++j) {
                int src = __shfl_sync(0xffffffffu, mysrc, j);
                float alpha = g_ws[(size_t)(start + b + j) * HH + h] * inv;
                uint2 zv = *(const uint2*)&g_zh[(size_t)src * DD + lane * 4];
                float2 p0 = __half22float2(*(__half2*)&zv.x);
                float2 p1 = __half22float2(*(__half2*)&zv.y);
                acc.x = fmaf(alpha, p0.x, acc.x);
                acc.y = fmaf(alpha, p0.y, acc.y);
                acc.z = fmaf(alpha, p1.x, acc.z);
                acc.w = fmaf(alpha, p1.y, acc.w);
            }
        }
    }
    *(float4*)&g_hagg[(size_t)n * DD + lane * 4] = acc;
}

// ---------------- elu + residual + LayerNorm (warp per node); ln out half ----------
__global__ void ln_kernel(const float* __restrict__ x,
                          const float* __restrict__ gamma, const float* __restrict__ beta) {
    int warp = threadIdx.x >> 5;
    int lane = threadIdx.x & 31;
    int n = blockIdx.x * 8 + warp;
    if (n >= NN) return;
    float4 hv = ((const float4*)(g_hagg + n * DD))[lane];
    float4 xv = ((const float4*)(x + n * DD))[lane];
    float4 r;
    r.x = xv.x + (hv.x > 0.f ? hv.x : expm1f(hv.x));
    r.y = xv.y + (hv.y > 0.f ? hv.y : expm1f(hv.y));
    r.z = xv.z + (hv.z > 0.f ? hv.z : expm1f(hv.z));
    r.w = xv.w + (hv.w > 0.f ? hv.w : expm1f(hv.w));
    ((float4*)(g_hres + n * DD))[lane] = r;
    float sum = r.x + r.y + r.z + r.w;
    float sq = r.x * r.x + r.y * r.y + r.z * r.z + r.w * r.w;
#pragma unroll
    for (int o = 16; o >= 1; o >>= 1) {
        sum += __shfl_xor_sync(0xffffffffu, sum, o);
        sq  += __shfl_xor_sync(0xffffffffu, sq, o);
    }
    float mu = sum * (1.f / 128.f);
    float var = sq * (1.f / 128.f) - mu * mu;
    float rstd = rsqrtf(var + 1e-5f);
    float4 gv = ((const float4*)gamma)[lane];
    float4 bv = ((const float4*)beta)[lane];
    float o0 = (r.x - mu) * rstd * gv.x + bv.x;
    float o1 = (r.y - mu) * rstd * gv.y + bv.y;
    float o2 = (r.z - mu) * rstd * gv.z + bv.z;
    float o3 = (r.w - mu) * rstd * gv.w + bv.w;
    uint2 ow;
    ow.x = f2h2(o0, o1);
    ow.y = f2h2(o2, o3);
    *(uint2*)&g_lnh[(size_t)n * DD + lane * 4] = ow;
}

// ---------------- launch ----------------
extern "C" void kernel_launch(void* const* d_in, const int* in_sizes, int n_in,
                              void* d_out, int out_size) {
    const float* x      = (const float*)d_in[0];
    const float* wfc    = (const float*)d_in[1];
    const float* a_l    = (const float*)d_in[2];
    const float* a_r    = (const float*)d_in[3];
    const float* gamma  = (const float*)d_in[4];
    const float* beta   = (const float*)d_in[5];
    const float* W1     = (const float*)d_in[6];
    const float* b1     = (const float*)d_in[7];
    const float* W2     = (const float*)d_in[8];
    const float* b2     = (const float*)d_in[9];
    const int* esrc     = (const int*)d_in[10];
    const int* edst     = (const int*)d_in[11];
    float* out          = (float*)d_out;

    void *p_zh, *p_lnh, *p_interh, *p_wtp, *p_w1p, *p_w2p;
    float* p_hres;
    cudaGetSymbolAddress(&p_zh, g_zh);
    cudaGetSymbolAddress(&p_lnh, g_lnh);
    cudaGetSymbolAddress(&p_interh, g_interh);
    cudaGetSymbolAddress(&p_wtp, g_wtp);
    cudaGetSymbolAddress(&p_w1p, g_w1p);
    cudaGetSymbolAddress(&p_w2p, g_w2p);
    cudaGetSymbolAddress((void**)&p_hres, g_hres);

    // order: prep(1), deg(2), scan1(3), tgemm0(4 = profiled slot), ...
    prep_kernel<<<(NN + 255) / 256, 256>>>(wfc, W1, W2);
    deg_kernel<<<(EE + 255) / 256, 256>>>(edst);
    scan1_kernel<<<NBLK_SCAN, 256>>>();

    // z = x @ WT  (A f32, C half)
    {
        dim3 grid((NN + 127) / 128, 1);
        tgemm_kernel<0, 0, 1><<<grid, 256>>>(x, (const uint32_t*)p_wtp, p_zh,
                                             NN, DD, DD, nullptr, nullptr);
    }
    scan2_kernel<<<1, 256>>>();
    eler_kernel<<<(NN * HH + 255) / 256, 256>>>(a_l, a_r);
    scatter_kernel<<<(EE + 255) / 256, 256>>>(esrc, edst);
    agg_kernel<<<(NN + 7) / 8, 256>>>();
    ln_kernel<<<(NN + 7) / 8, 256>>>(x, gamma, beta);

    // inter = relu(ln @ W1 + b1)  (A half, C half)
    {
        dim3 grid((NN + 127) / 128, DFF / 128);
        tgemm_kernel<1, 1, 1><<<grid, 256>>>(p_lnh, (const uint32_t*)p_w1p, p_interh,
                                             NN, DFF, DD, b1, nullptr);
    }
    // out = inter @ W2 + b2 + hres  (A half, C float)
    {
        dim3 grid((NN + 127) / 128, 1);
        tgemm_kernel<2, 1, 0><<<grid, 256>>>(p_interh, (const uint32_t*)p_w2p, out,
                                             NN, DD, DFF, b2, p_hres);
    }
}

// round 11
// speedup vs baseline: 1.7305x; 1.0261x over previous
#include <cuda_runtime.h>
#include <cuda_fp16.h>
#include <math.h>
#include <stdint.h>

#define NN 50000
#define DD 128
#define HH 8
#define DHH 16
#define EE 800000
#define DFF 512
#define NBLK_SCAN 196   // ceil(50000/256)

// ---------------- scratch (static device globals; no allocation) ----------------
__device__ __half    g_zh[NN * DD];
__device__ __half    g_lnh[NN * DD];
__device__ __half    g_interh[NN * DFF];
__device__ uint32_t  g_wtp[64 * DD];
__device__ uint32_t  g_w1p[64 * DFF];
__device__ uint32_t  g_w2p[256 * DD];
__device__ float g_el[NN * HH];
__device__ float g_er[NN * HH];
__device__ float g_ws[EE * HH];
__device__ int   g_srcs[EE];
__device__ int   g_deg[NN];
__device__ int   g_cursor[NN];
__device__ int   g_base[NN];
__device__ int   g_bsum[256];
__device__ int   g_boff[256];
__device__ float g_hagg[NN * DD];
__device__ float g_hres[NN * DD];

__device__ __forceinline__ uint32_t f2h2(float lo, float hi) {
    __half2 h = __floats2half2_rn(lo, hi);
    return *(uint32_t*)&h;
}

// ---------------- fused prep: zero counters + pair all weights ----------------
__global__ void prep_kernel(const float* __restrict__ wfc,
                            const float* __restrict__ W1,
                            const float* __restrict__ W2) {
    int i = blockIdx.x * blockDim.x + threadIdx.x;
    if (i < NN) { g_deg[i] = 0; g_cursor[i] = 0; }
    if (i < 64 * DD) {
        int dp = i >> 7;
        int col = i & 127;
        int h = col >> 4;
        int k = col & 15;
        float v0 = wfc[h * 2048 + (2 * dp) * 16 + k];
        float v1 = wfc[h * 2048 + (2 * dp + 1) * 16 + k];
        g_wtp[i] = f2h2(v0, v1);
    }
    if (i < 64 * DFF) {
        int n = i & (DFF - 1);
        int kp = i >> 9;
        g_w1p[i] = f2h2(W1[(size_t)(2 * kp) * DFF + n], W1[(size_t)(2 * kp + 1) * DFF + n]);
    }
    if (i < 256 * DD) {
        int n = i & (DD - 1);
        int kp = i >> 7;
        g_w2p[i] = f2h2(W2[(size_t)(2 * kp) * DD + n], W2[(size_t)(2 * kp + 1) * DD + n]);
    }
}

// ---------------- fp16 mma ----------------
__device__ __forceinline__ void mma_f16(float* c, const uint32_t* a, const uint32_t* b) {
    asm volatile(
        "mma.sync.aligned.m16n8k16.row.col.f32.f16.f16.f32 "
        "{%0,%1,%2,%3}, {%4,%5,%6,%7}, {%8,%9}, {%0,%1,%2,%3};"
        : "+f"(c[0]), "+f"(c[1]), "+f"(c[2]), "+f"(c[3])
        : "r"(a[0]), "r"(a[1]), "r"(a[2]), "r"(a[3]), "r"(b[0]), "r"(b[1]));
}

#define A_G_STRIDE 1028
#define B_U_STRIDE 66

// ---------------- fp16 tensor GEMM, 128x128 tile, 256 threads, smem dbuf ---------
template <int EPI, int AHALF, int CHALF>
__global__ void __launch_bounds__(256, 2) tgemm_kernel(
    const void* __restrict__ Av, const uint32_t* __restrict__ Bp, void* __restrict__ Cv,
    int M, int Nn, int K, const float* __restrict__ bias, const float* __restrict__ res)
{
    __shared__ uint32_t Af[2][2 * A_G_STRIDE];
    __shared__ uint32_t Bf[2][2 * 16 * B_U_STRIDE];

    const float* A32 = (const float*)Av;
    const __half* A16 = (const __half*)Av;
    float* Cf = (float*)Cv;
    __half* Ch = (__half*)Cv;

    const int tid = threadIdx.x;
    const int lane = tid & 31;
    const int wid = tid >> 5;
    const int wm = wid >> 2;
    const int wn = wid & 3;
    const int m0 = blockIdx.x * 128;
    const int n0 = blockIdx.y * 128;

    const int a_m = tid >> 3;
    const int a_kq = tid & 7;
    const int ah_m = tid >> 2;
    const int ah_q = tid & 3;
    const int b_p = tid >> 5;
    const int b_nq = tid & 31;

    uint32_t aw[8];
    uint4 avh[2];
    uint4 bv[2];

    auto ldg_chunk = [&](int k0) {
        if constexpr (AHALF) {
#pragma unroll
            for (int it = 0; it < 2; ++it) {
                int m = ah_m + it * 64;
                avh[it] = make_uint4(0, 0, 0, 0);
                if (m0 + m < M) avh[it] = *(const uint4*)&A16[(size_t)(m0 + m) * K + k0 + ah_q * 8];
            }
        } else {
#pragma unroll
            for (int it = 0; it < 4; ++it) {
                int ml = a_m + it * 32;
                float4 v = make_float4(0.f, 0.f, 0.f, 0.f);
                if (m0 + ml < M) v = *(const float4*)&A32[(size_t)(m0 + ml) * K + k0 + a_kq * 4];
                aw[it * 2 + 0] = f2h2(v.x, v.y);
                aw[it * 2 + 1] = f2h2(v.z, v.w);
            }
        }
        const int kp0 = k0 >> 1;
#pragma unroll
        for (int it = 0; it < 2; ++it) {
            int p = b_p + 8 * it;
            bv[it] = *(const uint4*)&Bp[(size_t)(kp0 + p) * Nn + n0 + b_nq * 4];
        }
    };

    auto sts_chunk = [&](int buf) {
        if constexpr (AHALF) {
#pragma unroll
            for (int it = 0; it < 2; ++it) {
                int m = ah_m + it * 64;
                int t4 = m >> 4;
                int mr = m & 15;
                const uint32_t* w = (const uint32_t*)&avh[it];
#pragma unroll
                for (int j = 0; j < 4; ++j) {
                    int p = 4 * ah_q + j;
                    int g = p >> 3, pl = p & 7;
                    int lw = (mr & 7) * 4 + (pl & 3);
                    int iw = (mr >> 3) + 2 * (pl >> 2);
                    Af[buf][g * A_G_STRIDE + t4 * 128 + lw * 4 + iw] = w[j];
                }
            }
        } else {
#pragma unroll
            for (int it = 0; it < 4; ++it) {
                int ml = a_m + it * 32;
                int t4 = ml >> 4;
                int mr = ml & 15;
#pragma unroll
                for (int j = 0; j < 2; ++j) {
                    int p = 2 * a_kq + j;
                    int g = p >> 3, pl = p & 7;
                    int lw = (mr & 7) * 4 + (pl & 3);
                    int iw = (mr >> 3) + 2 * (pl >> 2);
                    Af[buf][g * A_G_STRIDE + t4 * 128 + lw * 4 + iw] = aw[it * 2 + j];
                }
            }
        }
#pragma unroll
        for (int it = 0; it < 2; ++it) {
            int p = b_p + 8 * it;
            int g = p >> 3, pl = p & 7;
            const uint32_t* w = (const uint32_t*)&bv[it];
#pragma unroll
            for (int j = 0; j < 4; ++j) {
                int n = 4 * b_nq + j;
                int u = n >> 3, nl = n & 7;
                int lw = nl * 4 + (pl & 3);
                int iw = pl >> 2;
                Bf[buf][(g * 16 + u) * B_U_STRIDE + lw * 2 + iw] = w[j];
            }
        }
    };

    float acc[4][4][4];
#pragma unroll
    for (int i = 0; i < 4; ++i)
#pragma unroll
        for (int j = 0; j < 4; ++j)
#pragma unroll
            for (int r = 0; r < 4; ++r) acc[i][j][r] = 0.f;

    auto mma_chunk = [&](int buf) {
#pragma unroll
        for (int g = 0; g < 2; ++g) {
            uint32_t af[4][4], bf[4][2];
#pragma unroll
            for (int mt = 0; mt < 4; ++mt)
                *(uint4*)af[mt] = *(const uint4*)&Af[buf][g * A_G_STRIDE + (wm * 4 + mt) * 128 + lane * 4];
#pragma unroll
            for (int nt = 0; nt < 4; ++nt)
                *(uint2*)bf[nt] = *(const uint2*)&Bf[buf][(g * 16 + wn * 4 + nt) * B_U_STRIDE + lane * 2];
#pragma unroll
            for (int mt = 0; mt < 4; ++mt)
#pragma unroll
                for (int nt = 0; nt < 4; ++nt)
                    mma_f16(acc[mt][nt], af[mt], bf[nt]);
        }
    };

    const int CHUNKS = K >> 5;
    ldg_chunk(0);
    sts_chunk(0);
    __syncthreads();
    for (int c = 1; c < CHUNKS; ++c) {
        ldg_chunk(c * 32);
        mma_chunk((c - 1) & 1);
        sts_chunk(c & 1);
        __syncthreads();
    }
    mma_chunk((CHUNKS - 1) & 1);

    // epilogue
    const int lr = lane >> 2;
    const int lc = lane & 3;
#pragma unroll
    for (int mt = 0; mt < 4; ++mt) {
#pragma unroll
        for (int nt = 0; nt < 4; ++nt) {
            int row = m0 + wm * 64 + mt * 16 + lr;
            int col = n0 + wn * 32 + nt * 8 + 2 * lc;
            float c0 = acc[mt][nt][0], c1 = acc[mt][nt][1];
            float c2 = acc[mt][nt][2], c3 = acc[mt][nt][3];
            if (EPI == 1) {
                float b0 = bias[col], b1 = bias[col + 1];
                c0 = fmaxf(c0 + b0, 0.f); c1 = fmaxf(c1 + b1, 0.f);
                c2 = fmaxf(c2 + b0, 0.f); c3 = fmaxf(c3 + b1, 0.f);
            }
            if (EPI == 2) {
                float b0 = bias[col], b1 = bias[col + 1];
                if (row < M) {
                    c0 += b0 + res[(size_t)row * Nn + col];
                    c1 += b1 + res[(size_t)row * Nn + col + 1];
                }
                if (row + 8 < M) {
                    c2 += b0 + res[(size_t)(row + 8) * Nn + col];
                    c3 += b1 + res[(size_t)(row + 8) * Nn + col + 1];
                }
            }
            if (CHALF) {
                if (row < M)     *(uint32_t*)&Ch[(size_t)row * Nn + col]       = f2h2(c0, c1);
                if (row + 8 < M) *(uint32_t*)&Ch[(size_t)(row + 8) * Nn + col] = f2h2(c2, c3);
            } else {
                if (row < M)     *(float2*)&Cf[(size_t)row * Nn + col]       = make_float2(c0, c1);
                if (row + 8 < M) *(float2*)&Cf[(size_t)(row + 8) * Nn + col] = make_float2(c2, c3);
            }
        }
    }
}

// ---------------- el / er: one thread per (node, head), z half ----------------
__global__ void eler_kernel(const float* __restrict__ a_l, const float* __restrict__ a_r) {
    int idx = blockIdx.x * blockDim.x + threadIdx.x;
    if (idx >= NN * HH) return;
    int n = idx >> 3;
    int h = idx & 7;
    const uint32_t* zw = (const uint32_t*)&g_zh[n * DD + h * DHH];
    uint4 z0 = *(const uint4*)zw;
    uint4 z1 = *(const uint4*)(zw + 4);
    uint32_t w[8] = {z0.x, z0.y, z0.z, z0.w, z1.x, z1.y, z1.z, z1.w};
    const float* lp = &a_l[h * DHH];
    const float* rp = &a_r[h * DHH];
    float pl = 0.f, pr = 0.f;
#pragma unroll
    for (int q = 0; q < 8; ++q) {
        float2 f = __half22float2(*(__half2*)&w[q]);
        pl += f.x * lp[2 * q] + f.y * lp[2 * q + 1];
        pr += f.x * rp[2 * q] + f.y * rp[2 * q + 1];
    }
    g_el[idx] = pl;
    g_er[idx] = pr;
}

// ---------------- degree histogram ----------------
__global__ void deg_kernel(const int* __restrict__ edst) {
    int e = blockIdx.x * blockDim.x + threadIdx.x;
    if (e >= EE) return;
    atomicAdd(&g_deg[edst[e]], 1);
}

// ---------------- scan (2 kernels; block-offset add folded into consumers) -------
__global__ void scan1_kernel() {
    __shared__ int sh[256];
    int t = threadIdx.x;
    int i = blockIdx.x * 256 + t;
    int v = (i < NN) ? g_deg[i] : 0;
    sh[t] = v;
    __syncthreads();
#pragma unroll
    for (int off = 1; off < 256; off <<= 1) {
        int x = (t >= off) ? sh[t - off] : 0;
        __syncthreads();
        sh[t] += x;
        __syncthreads();
    }
    if (i < NN) g_base[i] = sh[t] - v;
    if (t == 255) g_bsum[blockIdx.x] = sh[255];
}
__global__ void scan2_kernel() {
    __shared__ int sh[256];
    int t = threadIdx.x;
    int v = (t < NBLK_SCAN) ? g_bsum[t] : 0;
    sh[t] = v;
    __syncthreads();
#pragma unroll
    for (int off = 1; off < 256; off <<= 1) {
        int x = (t >= off) ? sh[t - off] : 0;
        __syncthreads();
        sh[t] += x;
        __syncthreads();
    }
    g_boff[t] = sh[t] - v;
}

// ---------------- scatter edges into CSR slots + compute head weights ----------------
__global__ void scatter_kernel(const int* __restrict__ esrc, const int* __restrict__ edst) {
    int e = blockIdx.x * blockDim.x + threadIdx.x;
    if (e >= EE) return;
    int s = esrc[e], d = edst[e];
    int pos = g_base[d] + g_boff[d >> 8] + atomicAdd(&g_cursor[d], 1);
    g_srcs[pos] = s;
    float4 el0 = *(const float4*)&g_el[s * HH];
    float4 el1 = *(const float4*)&g_el[s * HH + 4];
    float4 er0 = *(const float4*)&g_er[d * HH];
    float4 er1 = *(const float4*)&g_er[d * HH + 4];
    float ev[8] = {el0.x + er0.x, el0.y + er0.y, el0.z + er0.z, el0.w + er0.w,
                   el1.x + er1.x, el1.y + er1.y, el1.z + er1.z, el1.w + er1.w};
    float w[8];
#pragma unroll
    for (int h = 0; h < 8; ++h) {
        float v = ev[h];
        v = (v > 0.f) ? v : 0.01f * v;
        w[h] = __expf(v);
    }
    *(float4*)&g_ws[(size_t)pos * HH]     = make_float4(w[0], w[1], w[2], w[3]);
    *(float4*)&g_ws[(size_t)pos * HH + 4] = make_float4(w[4], w[5], w[6], w[7]);
}

// ---------------- warp-per-node aggregation (no atomics, src prefetch) ----------
__global__ void __launch_bounds__(256) agg_kernel() {
    int n = blockIdx.x * 8 + (threadIdx.x >> 5);
    int lane = threadIdx.x & 31;
    if (n >= NN) return;
    int start = g_base[n] + g_boff[n >> 8];
    int deg = g_deg[n];
    float4 acc = make_float4(0.f, 0.f, 0.f, 0.f);
    if (deg > 0) {
        float s0 = 0.f, s1 = 0.f, s2 = 0.f, s3 = 0.f;
        float s4 = 0.f, s5 = 0.f, s6 = 0.f, s7 = 0.f;
        for (int i = start + lane; i < start + deg; i += 32) {
            float4 wa = *(const float4*)&g_ws[(size_t)i * HH];
            float4 wb = *(const float4*)&g_ws[(size_t)i * HH + 4];
            s0 += wa.x; s1 += wa.y; s2 += wa.z; s3 += wa.w;
            s4 += wb.x; s5 += wb.y; s6 += wb.z; s7 += wb.w;
        }
#pragma unroll
        for (int o = 16; o >= 1; o >>= 1) {
            s0 += __shfl_xor_sync(0xffffffffu, s0, o);
            s1 += __shfl_xor_sync(0xffffffffu, s1, o);
            s2 += __shfl_xor_sync(0xffffffffu, s2, o);
            s3 += __shfl_xor_sync(0xffffffffu, s3, o);
            s4 += __shfl_xor_sync(0xffffffffu, s4, o);
            s5 += __shfl_xor_sync(0xffffffffu, s5, o);
            s6 += __shfl_xor_sync(0xffffffffu, s6, o);
            s7 += __shfl_xor_sync(0xffffffffu, s7, o);
        }
        int h = lane >> 2;
        float sv;
        switch (h) {
            case 0: sv = s0; break;
            case 1: sv = s1; break;
            case 2: sv = s2; break;
            case 3: sv = s3; break;
            case 4: sv = s4; break;
            case 5: sv = s5; break;
            case 6: sv = s6; break;
            default: sv = s7; break;
        }
        float inv = 1.f / fmaxf(sv, 1e-9f);
        for (int b = 0; b < deg; b += 32) {
            int cnt = min(32, deg - b);
            int mysrc = (lane < cnt) ? g_srcs[start + b + lane] : 0;
#pragma unroll 4
            for (int j = 0; j < cnt; ++j) {
                int src = __shfl_sync(0xffffffffu, mysrc, j);
                float alpha = g_ws[(size_t)(start + b + j) * HH + h] * inv;
                uint2 zv = *(const uint2*)&g_zh[(size_t)src * DD + lane * 4];
                float2 p0 = __half22float2(*(__half2*)&zv.x);
                float2 p1 = __half22float2(*(__half2*)&zv.y);
                acc.x = fmaf(alpha, p0.x, acc.x);
                acc.y = fmaf(alpha, p0.y, acc.y);
                acc.z = fmaf(alpha, p1.x, acc.z);
                acc.w = fmaf(alpha, p1.y, acc.w);
            }
        }
    }
    *(float4*)&g_hagg[(size_t)n * DD + lane * 4] = acc;
}

// ---------------- elu + residual + LayerNorm (warp per node); ln out half ----------
__global__ void ln_kernel(const float* __restrict__ x,
                          const float* __restrict__ gamma, const float* __restrict__ beta) {
    int warp = threadIdx.x >> 5;
    int lane = threadIdx.x & 31;
    int n = blockIdx.x * 8 + warp;
    if (n >= NN) return;
    float4 hv = ((const float4*)(g_hagg + n * DD))[lane];
    float4 xv = ((const float4*)(x + n * DD))[lane];
    float4 r;
    r.x = xv.x + (hv.x > 0.f ? hv.x : expm1f(hv.x));
    r.y = xv.y + (hv.y > 0.f ? hv.y : expm1f(hv.y));
    r.z = xv.z + (hv.z > 0.f ? hv.z : expm1f(hv.z));
    r.w = xv.w + (hv.w > 0.f ? hv.w : expm1f(hv.w));
    ((float4*)(g_hres + n * DD))[lane] = r;
    float sum = r.x + r.y + r.z + r.w;
    float sq = r.x * r.x + r.y * r.y + r.z * r.z + r.w * r.w;
#pragma unroll
    for (int o = 16; o >= 1; o >>= 1) {
        sum += __shfl_xor_sync(0xffffffffu, sum, o);
        sq  += __shfl_xor_sync(0xffffffffu, sq, o);
    }
    float mu = sum * (1.f / 128.f);
    float var = sq * (1.f / 128.f) - mu * mu;
    float rstd = rsqrtf(var + 1e-5f);
    float4 gv = ((const float4*)gamma)[lane];
    float4 bv = ((const float4*)beta)[lane];
    float o0 = (r.x - mu) * rstd * gv.x + bv.x;
    float o1 = (r.y - mu) * rstd * gv.y + bv.y;
    float o2 = (r.z - mu) * rstd * gv.z + bv.z;
    float o3 = (r.w - mu) * rstd * gv.w + bv.w;
    uint2 ow;
    ow.x = f2h2(o0, o1);
    ow.y = f2h2(o2, o3);
    *(uint2*)&g_lnh[(size_t)n * DD + lane * 4] = ow;
}

// ---------------- launch ----------------
extern "C" void kernel_launch(void* const* d_in, const int* in_sizes, int n_in,
                              void* d_out, int out_size) {
    const float* x      = (const float*)d_in[0];
    const float* wfc    = (const float*)d_in[1];
    const float* a_l    = (const float*)d_in[2];
    const float* a_r    = (const float*)d_in[3];
    const float* gamma  = (const float*)d_in[4];
    const float* beta   = (const float*)d_in[5];
    const float* W1     = (const float*)d_in[6];
    const float* b1     = (const float*)d_in[7];
    const float* W2     = (const float*)d_in[8];
    const float* b2     = (const float*)d_in[9];
    const int* esrc     = (const int*)d_in[10];
    const int* edst     = (const int*)d_in[11];
    float* out          = (float*)d_out;

    void *p_zh, *p_lnh, *p_interh, *p_wtp, *p_w1p, *p_w2p;
    float* p_hres;
    cudaGetSymbolAddress(&p_zh, g_zh);
    cudaGetSymbolAddress(&p_lnh, g_lnh);
    cudaGetSymbolAddress(&p_interh, g_interh);
    cudaGetSymbolAddress(&p_wtp, g_wtp);
    cudaGetSymbolAddress(&p_w1p, g_w1p);
    cudaGetSymbolAddress(&p_w2p, g_w2p);
    cudaGetSymbolAddress((void**)&p_hres, g_hres);

    // side stream + events (host-side resources, created once; identical work per call)
    static cudaStream_t s1 = nullptr;
    static cudaEvent_t ev_fork = nullptr, ev_join = nullptr;
    if (s1 == nullptr) {
        cudaStreamCreateWithFlags(&s1, cudaStreamNonBlocking);
        cudaEventCreateWithFlags(&ev_fork, cudaEventDisableTiming);
        cudaEventCreateWithFlags(&ev_join, cudaEventDisableTiming);
    }

    // fork: CSR-build chain (deg->scan1->scan2) runs on s1 concurrently with
    // prep->gemm0->eler on the main stream. Join before scatter.
    cudaEventRecord(ev_fork, 0);
    cudaStreamWaitEvent(s1, ev_fork, 0);

    prep_kernel<<<(NN + 255) / 256, 256>>>(wfc, W1, W2);            // launch 1 (main)
    deg_kernel<<<(EE + 255) / 256, 256, 0, s1>>>(edst);             // launch 2 (s1)
    scan1_kernel<<<NBLK_SCAN, 256, 0, s1>>>();                      // launch 3 (s1)

    // z = x @ WT  (A f32, C half)   — launch 4 = profiled slot
    {
        dim3 grid((NN + 127) / 128, 1);
        tgemm_kernel<0, 0, 1><<<grid, 256>>>(x, (const uint32_t*)p_wtp, p_zh,
                                             NN, DD, DD, nullptr, nullptr);
    }
    scan2_kernel<<<1, 256, 0, s1>>>();                              // launch 5 (s1)
    eler_kernel<<<(NN * HH + 255) / 256, 256>>>(a_l, a_r);          // launch 6 (main)

    cudaEventRecord(ev_join, s1);
    cudaStreamWaitEvent(0, ev_join, 0);

    scatter_kernel<<<(EE + 255) / 256, 256>>>(esrc, edst);
    agg_kernel<<<(NN + 7) / 8, 256>>>();
    ln_kernel<<<(NN + 7) / 8, 256>>>(x, gamma, beta);

    // inter = relu(ln @ W1 + b1)  (A half, C half)
    {
        dim3 grid((NN + 127) / 128, DFF / 128);
        tgemm_kernel<1, 1, 1><<<grid, 256>>>(p_lnh, (const uint32_t*)p_w1p, p_interh,
                                             NN, DFF, DD, b1, nullptr);
    }
    // out = inter @ W2 + b2 + hres  (A half, C float)
    {
        dim3 grid((NN + 127) / 128, 1);
        tgemm_kernel<2, 1, 0><<<grid, 256>>>(p_interh, (const uint32_t*)p_w2p, out,
                                             NN, DD, DFF, b2, p_hres);
    }
}

// round 12
// speedup vs baseline: 1.7492x; 1.0108x over previous
#include <cuda_runtime.h>
#include <cuda_fp16.h>
#include <math.h>
#include <stdint.h>

#define NN 50000
#define DD 128
#define HH 8
#define DHH 16
#define EE 800000
#define DFF 512
#define NBLK_SCAN 196   // ceil(50000/256)

// ---------------- scratch (static device globals; no allocation) ----------------
__device__ __half    g_zh[NN * DD];
__device__ __half    g_lnh[NN * DD];
__device__ __half    g_interh[NN * DFF];
__device__ uint32_t  g_wtp[64 * DD];
__device__ uint32_t  g_w1p[64 * DFF];
__device__ uint32_t  g_w2p[256 * DD];
__device__ float g_el[NN * HH];
__device__ float g_er[NN * HH];
__device__ uint32_t g_wsh[EE * 4];     // edge weights, half2 x4 per edge
__device__ int   g_srcs[EE];
__device__ int   g_deg[NN];
__device__ int   g_cursor[NN];
__device__ int   g_base[NN];
__device__ int   g_bsum[256];
__device__ int   g_boff[256];
__device__ float g_hres[NN * DD];

__device__ __forceinline__ uint32_t f2h2(float lo, float hi) {
    __half2 h = __floats2half2_rn(lo, hi);
    return *(uint32_t*)&h;
}

// ---------------- fused prep: zero counters + pair all weights ----------------
__global__ void prep_kernel(const float* __restrict__ wfc,
                            const float* __restrict__ W1,
                            const float* __restrict__ W2) {
    int i = blockIdx.x * blockDim.x + threadIdx.x;
    if (i < NN) { g_deg[i] = 0; g_cursor[i] = 0; }
    if (i < 64 * DD) {
        int dp = i >> 7;
        int col = i & 127;
        int h = col >> 4;
        int k = col & 15;
        float v0 = wfc[h * 2048 + (2 * dp) * 16 + k];
        float v1 = wfc[h * 2048 + (2 * dp + 1) * 16 + k];
        g_wtp[i] = f2h2(v0, v1);
    }
    if (i < 64 * DFF) {
        int n = i & (DFF - 1);
        int kp = i >> 9;
        g_w1p[i] = f2h2(W1[(size_t)(2 * kp) * DFF + n], W1[(size_t)(2 * kp + 1) * DFF + n]);
    }
    if (i < 256 * DD) {
        int n = i & (DD - 1);
        int kp = i >> 7;
        g_w2p[i] = f2h2(W2[(size_t)(2 * kp) * DD + n], W2[(size_t)(2 * kp + 1) * DD + n]);
    }
}

// ---------------- fp16 mma ----------------
__device__ __forceinline__ void mma_f16(float* c, const uint32_t* a, const uint32_t* b) {
    asm volatile(
        "mma.sync.aligned.m16n8k16.row.col.f32.f16.f16.f32 "
        "{%0,%1,%2,%3}, {%4,%5,%6,%7}, {%8,%9}, {%0,%1,%2,%3};"
        : "+f"(c[0]), "+f"(c[1]), "+f"(c[2]), "+f"(c[3])
        : "r"(a[0]), "r"(a[1]), "r"(a[2]), "r"(a[3]), "r"(b[0]), "r"(b[1]));
}

#define A_G_STRIDE 1028
#define B_U_STRIDE 66

// ---------------- fp16 tensor GEMM, 128x128 tile, 256 threads, smem dbuf ---------
template <int EPI, int AHALF, int CHALF>
__global__ void __launch_bounds__(256, 2) tgemm_kernel(
    const void* __restrict__ Av, const uint32_t* __restrict__ Bp, void* __restrict__ Cv,
    int M, int Nn, int K, const float* __restrict__ bias, const float* __restrict__ res)
{
    __shared__ uint32_t Af[2][2 * A_G_STRIDE];
    __shared__ uint32_t Bf[2][2 * 16 * B_U_STRIDE];

    const float* A32 = (const float*)Av;
    const __half* A16 = (const __half*)Av;
    float* Cf = (float*)Cv;
    __half* Ch = (__half*)Cv;

    const int tid = threadIdx.x;
    const int lane = tid & 31;
    const int wid = tid >> 5;
    const int wm = wid >> 2;
    const int wn = wid & 3;
    const int m0 = blockIdx.x * 128;
    const int n0 = blockIdx.y * 128;

    const int a_m = tid >> 3;
    const int a_kq = tid & 7;
    const int ah_m = tid >> 2;
    const int ah_q = tid & 3;
    const int b_p = tid >> 5;
    const int b_nq = tid & 31;

    uint32_t aw[8];
    uint4 avh[2];
    uint4 bv[2];

    auto ldg_chunk = [&](int k0) {
        if constexpr (AHALF) {
#pragma unroll
            for (int it = 0; it < 2; ++it) {
                int m = ah_m + it * 64;
                avh[it] = make_uint4(0, 0, 0, 0);
                if (m0 + m < M) avh[it] = *(const uint4*)&A16[(size_t)(m0 + m) * K + k0 + ah_q * 8];
            }
        } else {
#pragma unroll
            for (int it = 0; it < 4; ++it) {
                int ml = a_m + it * 32;
                float4 v = make_float4(0.f, 0.f, 0.f, 0.f);
                if (m0 + ml < M) v = *(const float4*)&A32[(size_t)(m0 + ml) * K + k0 + a_kq * 4];
                aw[it * 2 + 0] = f2h2(v.x, v.y);
                aw[it * 2 + 1] = f2h2(v.z, v.w);
            }
        }
        const int kp0 = k0 >> 1;
#pragma unroll
        for (int it = 0; it < 2; ++it) {
            int p = b_p + 8 * it;
            bv[it] = *(const uint4*)&Bp[(size_t)(kp0 + p) * Nn + n0 + b_nq * 4];
        }
    };

    auto sts_chunk = [&](int buf) {
        if constexpr (AHALF) {
#pragma unroll
            for (int it = 0; it < 2; ++it) {
                int m = ah_m + it * 64;
                int t4 = m >> 4;
                int mr = m & 15;
                const uint32_t* w = (const uint32_t*)&avh[it];
#pragma unroll
                for (int j = 0; j < 4; ++j) {
                    int p = 4 * ah_q + j;
                    int g = p >> 3, pl = p & 7;
                    int lw = (mr & 7) * 4 + (pl & 3);
                    int iw = (mr >> 3) + 2 * (pl >> 2);
                    Af[buf][g * A_G_STRIDE + t4 * 128 + lw * 4 + iw] = w[j];
                }
            }
        } else {
#pragma unroll
            for (int it = 0; it < 4; ++it) {
                int ml = a_m + it * 32;
                int t4 = ml >> 4;
                int mr = ml & 15;
#pragma unroll
                for (int j = 0; j < 2; ++j) {
                    int p = 2 * a_kq + j;
                    int g = p >> 3, pl = p & 7;
                    int lw = (mr & 7) * 4 + (pl & 3);
                    int iw = (mr >> 3) + 2 * (pl >> 2);
                    Af[buf][g * A_G_STRIDE + t4 * 128 + lw * 4 + iw] = aw[it * 2 + j];
                }
            }
        }
#pragma unroll
        for (int it = 0; it < 2; ++it) {
            int p = b_p + 8 * it;
            int g = p >> 3, pl = p & 7;
            const uint32_t* w = (const uint32_t*)&bv[it];
#pragma unroll
            for (int j = 0; j < 4; ++j) {
                int n = 4 * b_nq + j;
                int u = n >> 3, nl = n & 7;
                int lw = nl * 4 + (pl & 3);
                int iw = pl >> 2;
                Bf[buf][(g * 16 + u) * B_U_STRIDE + lw * 2 + iw] = w[j];
            }
        }
    };

    float acc[4][4][4];
#pragma unroll
    for (int i = 0; i < 4; ++i)
#pragma unroll
        for (int j = 0; j < 4; ++j)
#pragma unroll
            for (int r = 0; r < 4; ++r) acc[i][j][r] = 0.f;

    auto mma_chunk = [&](int buf) {
#pragma unroll
        for (int g = 0; g < 2; ++g) {
            uint32_t af[4][4], bf[4][2];
#pragma unroll
            for (int mt = 0; mt < 4; ++mt)
                *(uint4*)af[mt] = *(const uint4*)&Af[buf][g * A_G_STRIDE + (wm * 4 + mt) * 128 + lane * 4];
#pragma unroll
            for (int nt = 0; nt < 4; ++nt)
                *(uint2*)bf[nt] = *(const uint2*)&Bf[buf][(g * 16 + wn * 4 + nt) * B_U_STRIDE + lane * 2];
#pragma unroll
            for (int mt = 0; mt < 4; ++mt)
#pragma unroll
                for (int nt = 0; nt < 4; ++nt)
                    mma_f16(acc[mt][nt], af[mt], bf[nt]);
        }
    };

    const int CHUNKS = K >> 5;
    ldg_chunk(0);
    sts_chunk(0);
    __syncthreads();
    for (int c = 1; c < CHUNKS; ++c) {
        ldg_chunk(c * 32);
        mma_chunk((c - 1) & 1);
        sts_chunk(c & 1);
        __syncthreads();
    }
    mma_chunk((CHUNKS - 1) & 1);

    // epilogue
    const int lr = lane >> 2;
    const int lc = lane & 3;
#pragma unroll
    for (int mt = 0; mt < 4; ++mt) {
#pragma unroll
        for (int nt = 0; nt < 4; ++nt) {
            int row = m0 + wm * 64 + mt * 16 + lr;
            int col = n0 + wn * 32 + nt * 8 + 2 * lc;
            float c0 = acc[mt][nt][0], c1 = acc[mt][nt][1];
            float c2 = acc[mt][nt][2], c3 = acc[mt][nt][3];
            if (EPI == 1) {
                float b0 = bias[col], b1 = bias[col + 1];
                c0 = fmaxf(c0 + b0, 0.f); c1 = fmaxf(c1 + b1, 0.f);
                c2 = fmaxf(c2 + b0, 0.f); c3 = fmaxf(c3 + b1, 0.f);
            }
            if (EPI == 2) {
                float b0 = bias[col], b1 = bias[col + 1];
                if (row < M) {
                    c0 += b0 + res[(size_t)row * Nn + col];
                    c1 += b1 + res[(size_t)row * Nn + col + 1];
                }
                if (row + 8 < M) {
                    c2 += b0 + res[(size_t)(row + 8) * Nn + col];
                    c3 += b1 + res[(size_t)(row + 8) * Nn + col + 1];
                }
            }
            if (CHALF) {
                if (row < M)     *(uint32_t*)&Ch[(size_t)row * Nn + col]       = f2h2(c0, c1);
                if (row + 8 < M) *(uint32_t*)&Ch[(size_t)(row + 8) * Nn + col] = f2h2(c2, c3);
            } else {
                if (row < M)     *(float2*)&Cf[(size_t)row * Nn + col]       = make_float2(c0, c1);
                if (row + 8 < M) *(float2*)&Cf[(size_t)(row + 8) * Nn + col] = make_float2(c2, c3);
            }
        }
    }
}

// ---------------- el / er: one thread per (node, head), z half ----------------
__global__ void eler_kernel(const float* __restrict__ a_l, const float* __restrict__ a_r) {
    int idx = blockIdx.x * blockDim.x + threadIdx.x;
    if (idx >= NN * HH) return;
    int n = idx >> 3;
    int h = idx & 7;
    const uint32_t* zw = (const uint32_t*)&g_zh[n * DD + h * DHH];
    uint4 z0 = *(const uint4*)zw;
    uint4 z1 = *(const uint4*)(zw + 4);
    uint32_t w[8] = {z0.x, z0.y, z0.z, z0.w, z1.x, z1.y, z1.z, z1.w};
    const float* lp = &a_l[h * DHH];
    const float* rp = &a_r[h * DHH];
    float pl = 0.f, pr = 0.f;
#pragma unroll
    for (int q = 0; q < 8; ++q) {
        float2 f = __half22float2(*(__half2*)&w[q]);
        pl += f.x * lp[2 * q] + f.y * lp[2 * q + 1];
        pr += f.x * rp[2 * q] + f.y * rp[2 * q + 1];
    }
    g_el[idx] = pl;
    g_er[idx] = pr;
}

// ---------------- degree histogram ----------------
__global__ void deg_kernel(const int* __restrict__ edst) {
    int e = blockIdx.x * blockDim.x + threadIdx.x;
    if (e >= EE) return;
    atomicAdd(&g_deg[edst[e]], 1);
}

// ---------------- scan (2 kernels; block-offset add folded into consumers) -------
__global__ void scan1_kernel() {
    __shared__ int sh[256];
    int t = threadIdx.x;
    int i = blockIdx.x * 256 + t;
    int v = (i < NN) ? g_deg[i] : 0;
    sh[t] = v;
    __syncthreads();
#pragma unroll
    for (int off = 1; off < 256; off <<= 1) {
        int x = (t >= off) ? sh[t - off] : 0;
        __syncthreads();
        sh[t] += x;
        __syncthreads();
    }
    if (i < NN) g_base[i] = sh[t] - v;
    if (t == 255) g_bsum[blockIdx.x] = sh[255];
}
__global__ void scan2_kernel() {
    __shared__ int sh[256];
    int t = threadIdx.x;
    int v = (t < NBLK_SCAN) ? g_bsum[t] : 0;
    sh[t] = v;
    __syncthreads();
#pragma unroll
    for (int off = 1; off < 256; off <<= 1) {
        int x = (t >= off) ? sh[t - off] : 0;
        __syncthreads();
        sh[t] += x;
        __syncthreads();
    }
    g_boff[t] = sh[t] - v;
}

// ---------------- scatter edges into CSR slots + compute head weights (half2) ------
__global__ void scatter_kernel(const int* __restrict__ esrc, const int* __restrict__ edst) {
    int e = blockIdx.x * blockDim.x + threadIdx.x;
    if (e >= EE) return;
    int s = esrc[e], d = edst[e];
    int pos = g_base[d] + g_boff[d >> 8] + atomicAdd(&g_cursor[d], 1);
    g_srcs[pos] = s;
    float4 el0 = *(const float4*)&g_el[s * HH];
    float4 el1 = *(const float4*)&g_el[s * HH + 4];
    float4 er0 = *(const float4*)&g_er[d * HH];
    float4 er1 = *(const float4*)&g_er[d * HH + 4];
    float ev[8] = {el0.x + er0.x, el0.y + er0.y, el0.z + er0.z, el0.w + er0.w,
                   el1.x + er1.x, el1.y + er1.y, el1.z + er1.z, el1.w + er1.w};
    float w[8];
#pragma unroll
    for (int h = 0; h < 8; ++h) {
        float v = ev[h];
        v = (v > 0.f) ? v : 0.01f * v;
        w[h] = __expf(v);
    }
    uint4 wv;
    wv.x = f2h2(w[0], w[1]);
    wv.y = f2h2(w[2], w[3]);
    wv.z = f2h2(w[4], w[5]);
    wv.w = f2h2(w[6], w[7]);
    *(uint4*)&g_wsh[(size_t)pos * 4] = wv;
}

// ---------------- warp-per-node aggregation + elu + residual + LayerNorm ---------
__global__ void __launch_bounds__(256) agg_ln_kernel(
    const float* __restrict__ x,
    const float* __restrict__ gamma, const float* __restrict__ beta)
{
    int n = blockIdx.x * 8 + (threadIdx.x >> 5);
    int lane = threadIdx.x & 31;
    if (n >= NN) return;
    int start = g_base[n] + g_boff[n >> 8];
    int deg = g_deg[n];
    float4 acc = make_float4(0.f, 0.f, 0.f, 0.f);
    if (deg > 0) {
        float s0 = 0.f, s1 = 0.f, s2 = 0.f, s3 = 0.f;
        float s4 = 0.f, s5 = 0.f, s6 = 0.f, s7 = 0.f;
        for (int i = start + lane; i < start + deg; i += 32) {
            uint4 wv = *(const uint4*)&g_wsh[(size_t)i * 4];
            float2 a0 = __half22float2(*(__half2*)&wv.x);
            float2 a1 = __half22float2(*(__half2*)&wv.y);
            float2 a2 = __half22float2(*(__half2*)&wv.z);
            float2 a3 = __half22float2(*(__half2*)&wv.w);
            s0 += a0.x; s1 += a0.y; s2 += a1.x; s3 += a1.y;
            s4 += a2.x; s5 += a2.y; s6 += a3.x; s7 += a3.y;
        }
#pragma unroll
        for (int o = 16; o >= 1; o >>= 1) {
            s0 += __shfl_xor_sync(0xffffffffu, s0, o);
            s1 += __shfl_xor_sync(0xffffffffu, s1, o);
            s2 += __shfl_xor_sync(0xffffffffu, s2, o);
            s3 += __shfl_xor_sync(0xffffffffu, s3, o);
            s4 += __shfl_xor_sync(0xffffffffu, s4, o);
            s5 += __shfl_xor_sync(0xffffffffu, s5, o);
            s6 += __shfl_xor_sync(0xffffffffu, s6, o);
            s7 += __shfl_xor_sync(0xffffffffu, s7, o);
        }
        int h = lane >> 2;
        float sv;
        switch (h) {
            case 0: sv = s0; break;
            case 1: sv = s1; break;
            case 2: sv = s2; break;
            case 3: sv = s3; break;
            case 4: sv = s4; break;
            case 5: sv = s5; break;
            case 6: sv = s6; break;
            default: sv = s7; break;
        }
        float inv = 1.f / fmaxf(sv, 1e-9f);
        for (int b = 0; b < deg; b += 32) {
            int cnt = min(32, deg - b);
            int mysrc = (lane < cnt) ? g_srcs[start + b + lane] : 0;
#pragma unroll 4
            for (int j = 0; j < cnt; ++j) {
                int src = __shfl_sync(0xffffffffu, mysrc, j);
                uint32_t ww = g_wsh[(size_t)(start + b + j) * 4 + (h >> 1)];
                __half2 hw = *(__half2*)&ww;
                float wv = (h & 1) ? __high2float(hw) : __low2float(hw);
                float alpha = wv * inv;
                uint2 zv = *(const uint2*)&g_zh[(size_t)src * DD + lane * 4];
                float2 p0 = __half22float2(*(__half2*)&zv.x);
                float2 p1 = __half22float2(*(__half2*)&zv.y);
                acc.x = fmaf(alpha, p0.x, acc.x);
                acc.y = fmaf(alpha, p0.y, acc.y);
                acc.z = fmaf(alpha, p1.x, acc.z);
                acc.w = fmaf(alpha, p1.y, acc.w);
            }
        }
    }
    // ---- fused elu + residual + LayerNorm ----
    float4 xv = ((const float4*)(x + (size_t)n * DD))[lane];
    float4 r;
    r.x = xv.x + (acc.x > 0.f ? acc.x : expm1f(acc.x));
    r.y = xv.y + (acc.y > 0.f ? acc.y : expm1f(acc.y));
    r.z = xv.z + (acc.z > 0.f ? acc.z : expm1f(acc.z));
    r.w = xv.w + (acc.w > 0.f ? acc.w : expm1f(acc.w));
    ((float4*)(g_hres + (size_t)n * DD))[lane] = r;
    float sum = r.x + r.y + r.z + r.w;
    float sq = r.x * r.x + r.y * r.y + r.z * r.z + r.w * r.w;
#pragma unroll
    for (int o = 16; o >= 1; o >>= 1) {
        sum += __shfl_xor_sync(0xffffffffu, sum, o);
        sq  += __shfl_xor_sync(0xffffffffu, sq, o);
    }
    float mu = sum * (1.f / 128.f);
    float var = sq * (1.f / 128.f) - mu * mu;
    float rstd = rsqrtf(var + 1e-5f);
    float4 gv = ((const float4*)gamma)[lane];
    float4 bv = ((const float4*)beta)[lane];
    float o0 = (r.x - mu) * rstd * gv.x + bv.x;
    float o1 = (r.y - mu) * rstd * gv.y + bv.y;
    float o2 = (r.z - mu) * rstd * gv.z + bv.z;
    float o3 = (r.w - mu) * rstd * gv.w + bv.w;
    uint2 ow;
    ow.x = f2h2(o0, o1);
    ow.y = f2h2(o2, o3);
    *(uint2*)&g_lnh[(size_t)n * DD + lane * 4] = ow;
}

// ---------------- launch ----------------
extern "C" void kernel_launch(void* const* d_in, const int* in_sizes, int n_in,
                              void* d_out, int out_size) {
    const float* x      = (const float*)d_in[0];
    const float* wfc    = (const float*)d_in[1];
    const float* a_l    = (const float*)d_in[2];
    const float* a_r    = (const float*)d_in[3];
    const float* gamma  = (const float*)d_in[4];
    const float* beta   = (const float*)d_in[5];
    const float* W1     = (const float*)d_in[6];
    const float* b1     = (const float*)d_in[7];
    const float* W2     = (const float*)d_in[8];
    const float* b2     = (const float*)d_in[9];
    const int* esrc     = (const int*)d_in[10];
    const int* edst     = (const int*)d_in[11];
    float* out          = (float*)d_out;

    void *p_zh, *p_lnh, *p_interh, *p_wtp, *p_w1p, *p_w2p;
    float* p_hres;
    cudaGetSymbolAddress(&p_zh, g_zh);
    cudaGetSymbolAddress(&p_lnh, g_lnh);
    cudaGetSymbolAddress(&p_interh, g_interh);
    cudaGetSymbolAddress(&p_wtp, g_wtp);
    cudaGetSymbolAddress(&p_w1p, g_w1p);
    cudaGetSymbolAddress(&p_w2p, g_w2p);
    cudaGetSymbolAddress((void**)&p_hres, g_hres);

    static cudaStream_t s1 = nullptr;
    static cudaEvent_t ev_fork = nullptr, ev_join = nullptr;
    if (s1 == nullptr) {
        cudaStreamCreateWithFlags(&s1, cudaStreamNonBlocking);
        cudaEventCreateWithFlags(&ev_fork, cudaEventDisableTiming);
        cudaEventCreateWithFlags(&ev_join, cudaEventDisableTiming);
    }

    cudaEventRecord(ev_fork, 0);
    cudaStreamWaitEvent(s1, ev_fork, 0);

    prep_kernel<<<(NN + 255) / 256, 256>>>(wfc, W1, W2);            // 1 (main)
    deg_kernel<<<(EE + 255) / 256, 256, 0, s1>>>(edst);             // 2 (s1)
    scan1_kernel<<<NBLK_SCAN, 256, 0, s1>>>();                      // 3 (s1)

    // z = x @ WT  (A f32, C half)   — launch 4 = profiled slot
    {
        dim3 grid((NN + 127) / 128, 1);
        tgemm_kernel<0, 0, 1><<<grid, 256>>>(x, (const uint32_t*)p_wtp, p_zh,
                                             NN, DD, DD, nullptr, nullptr);
    }
    scan2_kernel<<<1, 256, 0, s1>>>();                              // 5 (s1)
    eler_kernel<<<(NN * HH + 255) / 256, 256>>>(a_l, a_r);          // 6 (main)

    cudaEventRecord(ev_join, s1);
    cudaStreamWaitEvent(0, ev_join, 0);

    scatter_kernel<<<(EE + 255) / 256, 256>>>(esrc, edst);          // 7
    agg_ln_kernel<<<(NN + 7) / 8, 256>>>(x, gamma, beta);           // 8

    // inter = relu(ln @ W1 + b1)  (A half, C half)
    {
        dim3 grid((NN + 127) / 128, DFF / 128);
        tgemm_kernel<1, 1, 1><<<grid, 256>>>(p_lnh, (const uint32_t*)p_w1p, p_interh,
                                             NN, DFF, DD, b1, nullptr);
    }
    // out = inter @ W2 + b2 + hres  (A half, C float)
    {
        dim3 grid((NN + 127) / 128, 1);
        tgemm_kernel<2, 1, 0><<<grid, 256>>>(p_interh, (const uint32_t*)p_w2p, out,
                                             NN, DD, DFF, b2, p_hres);
    }
}

// round 13
// speedup vs baseline: 1.8165x; 1.0385x over previous
#include <cuda_runtime.h>
#include <cuda_fp16.h>
#include <math.h>
#include <stdint.h>

#define NN 50000
#define DD 128
#define HH 8
#define DHH 16
#define EE 800000
#define DFF 512
#define NBLK_SCAN 196   // ceil(50000/256)
#define NTILES 391      // ceil(50000/128)

// ---------------- scratch (static device globals; no allocation) ----------------
__device__ __half    g_zh[NN * DD];              // z, half, row-major
__device__ uint32_t  g_lnf[NTILES * 4 * 2048];   // LN out, A-fragment layout (K=128)
__device__ uint32_t  g_intf[NTILES * 16 * 2048]; // FFN inter, A-fragment layout (K=512)
__device__ uint32_t  g_wtp[4 * 2048];            // W_fc^T, B-fragment layout [c][2048]
__device__ uint32_t  g_w1p[4 * 4 * 2048];        // W1, B-fragment [c][nt][2048]
__device__ uint32_t  g_w2p[16 * 2048];           // W2, B-fragment [c][2048]
__device__ float g_el[NN * HH];
__device__ float g_er[NN * HH];
__device__ uint32_t g_wsh[EE * 4];               // edge weights, half2 x4
__device__ int   g_srcs[EE];
__device__ int   g_deg[NN];
__device__ int   g_cursor[NN];
__device__ int   g_base[NN];
__device__ int   g_bsum[256];
__device__ int   g_boff[256];
__device__ float g_hres[NN * DD];

__device__ __forceinline__ uint32_t f2h2(float lo, float hi) {
    __half2 h = __floats2half2_rn(lo, hi);
    return *(uint32_t*)&h;
}

// decode B-frag word index (within 2048-word block) -> (k0, n_local)
__device__ __forceinline__ void bfrag_decode(int rest, int& g, int& pl, int& nloc) {
    int blk = rest >> 6, off = rest & 63;
    g = blk >> 4;
    int u = blk & 15;
    int lw = off >> 1, iw = off & 1;
    pl = (lw & 3) + 4 * iw;
    nloc = u * 8 + (lw >> 2);
}

// ---------------- fused prep: zero counters + build fragment-layout weights ------
__global__ void prep_kernel(const float* __restrict__ wfc,
                            const float* __restrict__ W1,
                            const float* __restrict__ W2) {
    int i = blockIdx.x * blockDim.x + threadIdx.x;
    if (i < NN) { g_deg[i] = 0; g_cursor[i] = 0; }
    if (i < 4 * 2048) {              // wtp: [c(4)][2048], B[k][n] = wfc[(n>>4)*2048 + k*16 + (n&15)]
        int c = i >> 11, rest = i & 2047;
        int g, pl, n;
        bfrag_decode(rest, g, pl, n);
        int k0 = c * 32 + (g * 8 + pl) * 2;
        float v0 = wfc[(n >> 4) * 2048 + k0 * 16 + (n & 15)];
        float v1 = wfc[(n >> 4) * 2048 + (k0 + 1) * 16 + (n & 15)];
        g_wtp[i] = f2h2(v0, v1);
    }
    if (i < 4 * 4 * 2048) {          // w1p: [c(4)][nt(4)][2048], B = W1[K=128, N=512]
        int c = i >> 13, nt = (i >> 11) & 3, rest = i & 2047;
        int g, pl, nl;
        bfrag_decode(rest, g, pl, nl);
        int n = nt * 128 + nl;
        int k0 = c * 32 + (g * 8 + pl) * 2;
        g_w1p[i] = f2h2(W1[(size_t)k0 * DFF + n], W1[(size_t)(k0 + 1) * DFF + n]);
    }
    if (i < 16 * 2048) {             // w2p: [c(16)][2048], B = W2[K=512, N=128]
        int c = i >> 11, rest = i & 2047;
        int g, pl, n;
        bfrag_decode(rest, g, pl, n);
        int k0 = c * 32 + (g * 8 + pl) * 2;
        g_w2p[i] = f2h2(W2[(size_t)k0 * DD + n], W2[(size_t)(k0 + 1) * DD + n]);
    }
}

// ---------------- fp16 mma ----------------
__device__ __forceinline__ void mma_f16(float* c, const uint32_t* a, const uint32_t* b) {
    asm volatile(
        "mma.sync.aligned.m16n8k16.row.col.f32.f16.f16.f32 "
        "{%0,%1,%2,%3}, {%4,%5,%6,%7}, {%8,%9}, {%0,%1,%2,%3};"
        : "+f"(c[0]), "+f"(c[1]), "+f"(c[2]), "+f"(c[3])
        : "r"(a[0]), "r"(a[1]), "r"(a[2]), "r"(a[3]), "r"(b[0]), "r"(b[1]));
}

#define A_G_STRIDE 1028   // 1024 + 4 pad
#define B_U_STRIDE 68     // 64 + 4 pad (16B-aligned blocks for STS.128)

// ---------------- fp16 tensor GEMM, 128x128 tile, 256 threads, smem dbuf ---------
// AFRAG: 0 = A f32 row-major, 1 = A pre-fragmented half (gmem [tile][chunk][2048])
// CMODE: 0 = f32 row-major, 1 = half row-major, 2 = half A-fragment for next GEMM
// EPI:   0 plain, 1 relu+bias, 2 bias+res
template <int EPI, int AFRAG, int CMODE>
__global__ void __launch_bounds__(256, 2) tgemm_kernel(
    const void* __restrict__ Av, const uint32_t* __restrict__ Bp, void* __restrict__ Cv,
    int M, int Nn, int K, const float* __restrict__ bias, const float* __restrict__ res)
{
    __shared__ uint32_t Af[2][2 * A_G_STRIDE];
    __shared__ uint32_t Bf[2][2 * 16 * B_U_STRIDE];

    const float* A32 = (const float*)Av;
    const uint32_t* Afr = (const uint32_t*)Av;
    float* Cf = (float*)Cv;
    __half* Ch = (__half*)Cv;
    uint32_t* Cfr = (uint32_t*)Cv;

    const int tid = threadIdx.x;
    const int lane = tid & 31;
    const int wid = tid >> 5;
    const int wm = wid >> 2;
    const int wn = wid & 3;
    const int m0 = blockIdx.x * 128;
    const int n0 = blockIdx.y * 128;
    const int KC = K >> 5;
    const int NT = Nn >> 7;

    // f32-A loader coords
    const int a_m = tid >> 3;
    const int a_kq = tid & 7;
    // vector-copy coords
    const int bblk = tid >> 4;
    const int boff = (4 * tid) & 63;

    uint32_t aw[8];
    uint4 av0, av1, bv0, bv1;

    auto ldg_chunk = [&](int c) {
        if constexpr (AFRAG) {
            const uint4* s = (const uint4*)(Afr + ((size_t)blockIdx.x * KC + c) * 2048);
            av0 = s[tid];
            av1 = s[tid + 256];
        } else {
            const int k0 = c * 32;
#pragma unroll
            for (int it = 0; it < 4; ++it) {
                int ml = a_m + it * 32;
                float4 v = make_float4(0.f, 0.f, 0.f, 0.f);
                if (m0 + ml < M) v = *(const float4*)&A32[(size_t)(m0 + ml) * K + k0 + a_kq * 4];
                aw[it * 2 + 0] = f2h2(v.x, v.y);
                aw[it * 2 + 1] = f2h2(v.z, v.w);
            }
        }
        const uint4* s = (const uint4*)(Bp + ((size_t)(c * NT + blockIdx.y)) * 2048);
        bv0 = s[tid];
        bv1 = s[tid + 256];
    };

    auto sts_chunk = [&](int buf) {
        if constexpr (AFRAG) {
            *(uint4*)&Af[buf][4 * tid] = av0;
            *(uint4*)&Af[buf][A_G_STRIDE + 4 * tid] = av1;
        } else {
#pragma unroll
            for (int it = 0; it < 4; ++it) {
                int ml = a_m + it * 32;
                int t4 = ml >> 4;
                int mr = ml & 15;
#pragma unroll
                for (int j = 0; j < 2; ++j) {
                    int p = 2 * a_kq + j;
                    int g = p >> 3, pl = p & 7;
                    int lw = (mr & 7) * 4 + (pl & 3);
                    int iw = (mr >> 3) + 2 * (pl >> 2);
                    Af[buf][g * A_G_STRIDE + t4 * 128 + lw * 4 + iw] = aw[it * 2 + j];
                }
            }
        }
        *(uint4*)&Bf[buf][bblk * B_U_STRIDE + boff] = bv0;
        *(uint4*)&Bf[buf][(16 + bblk) * B_U_STRIDE + boff] = bv1;
    };

    float acc[4][4][4];
#pragma unroll
    for (int i = 0; i < 4; ++i)
#pragma unroll
        for (int j = 0; j < 4; ++j)
#pragma unroll
            for (int r = 0; r < 4; ++r) acc[i][j][r] = 0.f;

    auto mma_chunk = [&](int buf) {
#pragma unroll
        for (int g = 0; g < 2; ++g) {
            uint32_t af[4][4], bf[4][2];
#pragma unroll
            for (int mt = 0; mt < 4; ++mt)
                *(uint4*)af[mt] = *(const uint4*)&Af[buf][g * A_G_STRIDE + (wm * 4 + mt) * 128 + lane * 4];
#pragma unroll
            for (int nt = 0; nt < 4; ++nt)
                *(uint2*)bf[nt] = *(const uint2*)&Bf[buf][(g * 16 + wn * 4 + nt) * B_U_STRIDE + lane * 2];
#pragma unroll
            for (int mt = 0; mt < 4; ++mt)
#pragma unroll
                for (int nt = 0; nt < 4; ++nt)
                    mma_f16(acc[mt][nt], af[mt], bf[nt]);
        }
    };

    ldg_chunk(0);
    sts_chunk(0);
    __syncthreads();
    for (int c = 1; c < KC; ++c) {
        ldg_chunk(c);
        mma_chunk((c - 1) & 1);
        sts_chunk(c & 1);
        __syncthreads();
    }
    mma_chunk((KC - 1) & 1);

    // epilogue
    const int lr = lane >> 2;
    const int lc = lane & 3;
#pragma unroll
    for (int mt = 0; mt < 4; ++mt) {
#pragma unroll
        for (int nt = 0; nt < 4; ++nt) {
            int row = m0 + wm * 64 + mt * 16 + lr;
            int col = n0 + wn * 32 + nt * 8 + 2 * lc;
            float c0 = acc[mt][nt][0], c1 = acc[mt][nt][1];
            float c2 = acc[mt][nt][2], c3 = acc[mt][nt][3];
            if (EPI == 1) {
                float b0 = bias[col], b1 = bias[col + 1];
                c0 = fmaxf(c0 + b0, 0.f); c1 = fmaxf(c1 + b1, 0.f);
                c2 = fmaxf(c2 + b0, 0.f); c3 = fmaxf(c3 + b1, 0.f);
            }
            if (EPI == 2) {
                float b0 = bias[col], b1 = bias[col + 1];
                if (row < M) {
                    c0 += b0 + res[(size_t)row * Nn + col];
                    c1 += b1 + res[(size_t)row * Nn + col + 1];
                }
                if (row + 8 < M) {
                    c2 += b0 + res[(size_t)(row + 8) * Nn + col];
                    c3 += b1 + res[(size_t)(row + 8) * Nn + col + 1];
                }
            }
            if (CMODE == 0) {
                if (row < M)     *(float2*)&Cf[(size_t)row * Nn + col]       = make_float2(c0, c1);
                if (row + 8 < M) *(float2*)&Cf[(size_t)(row + 8) * Nn + col] = make_float2(c2, c3);
            } else if (CMODE == 1) {
                if (row < M)     *(uint32_t*)&Ch[(size_t)row * Nn + col]       = f2h2(c0, c1);
                if (row + 8 < M) *(uint32_t*)&Ch[(size_t)(row + 8) * Nn + col] = f2h2(c2, c3);
            } else {
                // write A-fragment layout for the next GEMM (tile = blockIdx.x)
                int cc = col >> 5;
                int pw = (col >> 1) & 15;
                int gg = pw >> 3, pl = pw & 7;
                size_t base = ((size_t)blockIdx.x * (Nn >> 5) + cc) * 2048 + gg * 1024;
                int m = row & 127;
                int t4 = m >> 4, mr = m & 15;
                if (row < M)
                    Cfr[base + t4 * 128 + ((mr & 7) * 4 + (pl & 3)) * 4 + ((mr >> 3) + 2 * (pl >> 2))] = f2h2(c0, c1);
                int m2 = m + 8;
                int t42 = m2 >> 4, mr2 = m2 & 15;
                if (row + 8 < M)
                    Cfr[base + t42 * 128 + ((mr2 & 7) * 4 + (pl & 3)) * 4 + ((mr2 >> 3) + 2 * (pl >> 2))] = f2h2(c2, c3);
            }
        }
    }
}

// ---------------- el / er: one thread per (node, head), z half ----------------
__global__ void eler_kernel(const float* __restrict__ a_l, const float* __restrict__ a_r) {
    int idx = blockIdx.x * blockDim.x + threadIdx.x;
    if (idx >= NN * HH) return;
    int n = idx >> 3;
    int h = idx & 7;
    const uint32_t* zw = (const uint32_t*)&g_zh[n * DD + h * DHH];
    uint4 z0 = *(const uint4*)zw;
    uint4 z1 = *(const uint4*)(zw + 4);
    uint32_t w[8] = {z0.x, z0.y, z0.z, z0.w, z1.x, z1.y, z1.z, z1.w};
    const float* lp = &a_l[h * DHH];
    const float* rp = &a_r[h * DHH];
    float pl = 0.f, pr = 0.f;
#pragma unroll
    for (int q = 0; q < 8; ++q) {
        float2 f = __half22float2(*(__half2*)&w[q]);
        pl += f.x * lp[2 * q] + f.y * lp[2 * q + 1];
        pr += f.x * rp[2 * q] + f.y * rp[2 * q + 1];
    }
    g_el[idx] = pl;
    g_er[idx] = pr;
}

// ---------------- degree histogram ----------------
__global__ void deg_kernel(const int* __restrict__ edst) {
    int e = blockIdx.x * blockDim.x + threadIdx.x;
    if (e >= EE) return;
    atomicAdd(&g_deg[edst[e]], 1);
}

// ---------------- scan (2 kernels; block-offset add folded into consumers) -------
__global__ void scan1_kernel() {
    __shared__ int sh[256];
    int t = threadIdx.x;
    int i = blockIdx.x * 256 + t;
    int v = (i < NN) ? g_deg[i] : 0;
    sh[t] = v;
    __syncthreads();
#pragma unroll
    for (int off = 1; off < 256; off <<= 1) {
        int x = (t >= off) ? sh[t - off] : 0;
        __syncthreads();
        sh[t] += x;
        __syncthreads();
    }
    if (i < NN) g_base[i] = sh[t] - v;
    if (t == 255) g_bsum[blockIdx.x] = sh[255];
}
__global__ void scan2_kernel() {
    __shared__ int sh[256];
    int t = threadIdx.x;
    int v = (t < NBLK_SCAN) ? g_bsum[t] : 0;
    sh[t] = v;
    __syncthreads();
#pragma unroll
    for (int off = 1; off < 256; off <<= 1) {
        int x = (t >= off) ? sh[t - off] : 0;
        __syncthreads();
        sh[t] += x;
        __syncthreads();
    }
    g_boff[t] = sh[t] - v;
}

// ---------------- scatter edges into CSR slots + compute head weights (half2) ------
__global__ void scatter_kernel(const int* __restrict__ esrc, const int* __restrict__ edst) {
    int e = blockIdx.x * blockDim.x + threadIdx.x;
    if (e >= EE) return;
    int s = esrc[e], d = edst[e];
    int pos = g_base[d] + g_boff[d >> 8] + atomicAdd(&g_cursor[d], 1);
    g_srcs[pos] = s;
    float4 el0 = *(const float4*)&g_el[s * HH];
    float4 el1 = *(const float4*)&g_el[s * HH + 4];
    float4 er0 = *(const float4*)&g_er[d * HH];
    float4 er1 = *(const float4*)&g_er[d * HH + 4];
    float ev[8] = {el0.x + er0.x, el0.y + er0.y, el0.z + er0.z, el0.w + er0.w,
                   el1.x + er1.x, el1.y + er1.y, el1.z + er1.z, el1.w + er1.w};
    float w[8];
#pragma unroll
    for (int h = 0; h < 8; ++h) {
        float v = ev[h];
        v = (v > 0.f) ? v : 0.01f * v;
        w[h] = __expf(v);
    }
    uint4 wv;
    wv.x = f2h2(w[0], w[1]);
    wv.y = f2h2(w[2], w[3]);
    wv.z = f2h2(w[4], w[5]);
    wv.w = f2h2(w[6], w[7]);
    *(uint4*)&g_wsh[(size_t)pos * 4] = wv;
}

// ---------------- warp-per-node aggregation + elu + residual + LayerNorm ---------
__global__ void __launch_bounds__(256) agg_ln_kernel(
    const float* __restrict__ x,
    const float* __restrict__ gamma, const float* __restrict__ beta)
{
    int n = blockIdx.x * 8 + (threadIdx.x >> 5);
    int lane = threadIdx.x & 31;
    if (n >= NN) return;
    int start = g_base[n] + g_boff[n >> 8];
    int deg = g_deg[n];
    float4 acc = make_float4(0.f, 0.f, 0.f, 0.f);
    if (deg > 0) {
        float s0 = 0.f, s1 = 0.f, s2 = 0.f, s3 = 0.f;
        float s4 = 0.f, s5 = 0.f, s6 = 0.f, s7 = 0.f;
        for (int i = start + lane; i < start + deg; i += 32) {
            uint4 wv = *(const uint4*)&g_wsh[(size_t)i * 4];
            float2 a0 = __half22float2(*(__half2*)&wv.x);
            float2 a1 = __half22float2(*(__half2*)&wv.y);
            float2 a2 = __half22float2(*(__half2*)&wv.z);
            float2 a3 = __half22float2(*(__half2*)&wv.w);
            s0 += a0.x; s1 += a0.y; s2 += a1.x; s3 += a1.y;
            s4 += a2.x; s5 += a2.y; s6 += a3.x; s7 += a3.y;
        }
#pragma unroll
        for (int o = 16; o >= 1; o >>= 1) {
            s0 += __shfl_xor_sync(0xffffffffu, s0, o);
            s1 += __shfl_xor_sync(0xffffffffu, s1, o);
            s2 += __shfl_xor_sync(0xffffffffu, s2, o);
            s3 += __shfl_xor_sync(0xffffffffu, s3, o);
            s4 += __shfl_xor_sync(0xffffffffu, s4, o);
            s5 += __shfl_xor_sync(0xffffffffu, s5, o);
            s6 += __shfl_xor_sync(0xffffffffu, s6, o);
            s7 += __shfl_xor_sync(0xffffffffu, s7, o);
        }
        int h = lane >> 2;
        float sv;
        switch (h) {
            case 0: sv = s0; break;
            case 1: sv = s1; break;
            case 2: sv = s2; break;
            case 3: sv = s3; break;
            case 4: sv = s4; break;
            case 5: sv = s5; break;
            case 6: sv = s6; break;
            default: sv = s7; break;
        }
        float inv = 1.f / fmaxf(sv, 1e-9f);
        for (int b = 0; b < deg; b += 32) {
            int cnt = min(32, deg - b);
            int mysrc = (lane < cnt) ? g_srcs[start + b + lane] : 0;
#pragma unroll 4
            for (int j = 0; j < cnt; ++j) {
                int src = __shfl_sync(0xffffffffu, mysrc, j);
                uint32_t ww = g_wsh[(size_t)(start + b + j) * 4 + (h >> 1)];
                __half2 hw = *(__half2*)&ww;
                float wv = (h & 1) ? __high2float(hw) : __low2float(hw);
                float alpha = wv * inv;
                uint2 zv = *(const uint2*)&g_zh[(size_t)src * DD + lane * 4];
                float2 p0 = __half22float2(*(__half2*)&zv.x);
                float2 p1 = __half22float2(*(__half2*)&zv.y);
                acc.x = fmaf(alpha, p0.x, acc.x);
                acc.y = fmaf(alpha, p0.y, acc.y);
                acc.z = fmaf(alpha, p1.x, acc.z);
                acc.w = fmaf(alpha, p1.y, acc.w);
            }
        }
    }
    // ---- fused elu + residual + LayerNorm, output in A-fragment layout ----
    float4 xv = ((const float4*)(x + (size_t)n * DD))[lane];
    float4 r;
    r.x = xv.x + (acc.x > 0.f ? acc.x : expm1f(acc.x));
    r.y = xv.y + (acc.y > 0.f ? acc.y : expm1f(acc.y));
    r.z = xv.z + (acc.z > 0.f ? acc.z : expm1f(acc.z));
    r.w = xv.w + (acc.w > 0.f ? acc.w : expm1f(acc.w));
    ((float4*)(g_hres + (size_t)n * DD))[lane] = r;
    float sum = r.x + r.y + r.z + r.w;
    float sq = r.x * r.x + r.y * r.y + r.z * r.z + r.w * r.w;
#pragma unroll
    for (int o = 16; o >= 1; o >>= 1) {
        sum += __shfl_xor_sync(0xffffffffu, sum, o);
        sq  += __shfl_xor_sync(0xffffffffu, sq, o);
    }
    float mu = sum * (1.f / 128.f);
    float var = sq * (1.f / 128.f) - mu * mu;
    float rstd = rsqrtf(var + 1e-5f);
    float4 gv = ((const float4*)gamma)[lane];
    float4 bv = ((const float4*)beta)[lane];
    float o0 = (r.x - mu) * rstd * gv.x + bv.x;
    float o1 = (r.y - mu) * rstd * gv.y + bv.y;
    float o2 = (r.z - mu) * rstd * gv.z + bv.z;
    float o3 = (r.w - mu) * rstd * gv.w + bv.w;
    int T = n >> 7, m = n & 127, t4 = m >> 4, mr = m & 15;
    uint32_t wA = f2h2(o0, o1), wB = f2h2(o2, o3);
    {
        int p = 2 * lane;
        int c = p >> 4, pw = p & 15, g = pw >> 3, pl = pw & 7;
        g_lnf[((size_t)T * 4 + c) * 2048 + g * 1024 + t4 * 128 +
              ((mr & 7) * 4 + (pl & 3)) * 4 + ((mr >> 3) + 2 * (pl >> 2))] = wA;
    }
    {
        int p = 2 * lane + 1;
        int c = p >> 4, pw = p & 15, g = pw >> 3, pl = pw & 7;
        g_lnf[((size_t)T * 4 + c) * 2048 + g * 1024 + t4 * 128 +
              ((mr & 7) * 4 + (pl & 3)) * 4 + ((mr >> 3) + 2 * (pl >> 2))] = wB;
    }
}

// ---------------- launch ----------------
extern "C" void kernel_launch(void* const* d_in, const int* in_sizes, int n_in,
                              void* d_out, int out_size) {
    const float* x      = (const float*)d_in[0];
    const float* wfc    = (const float*)d_in[1];
    const float* a_l    = (const float*)d_in[2];
    const float* a_r    = (const float*)d_in[3];
    const float* gamma  = (const float*)d_in[4];
    const float* beta   = (const float*)d_in[5];
    const float* W1     = (const float*)d_in[6];
    const float* b1     = (const float*)d_in[7];
    const float* W2     = (const float*)d_in[8];
    const float* b2     = (const float*)d_in[9];
    const int* esrc     = (const int*)d_in[10];
    const int* edst     = (const int*)d_in[11];
    float* out          = (float*)d_out;

    void *p_zh, *p_lnf, *p_intf, *p_wtp, *p_w1p, *p_w2p;
    float* p_hres;
    cudaGetSymbolAddress(&p_zh, g_zh);
    cudaGetSymbolAddress(&p_lnf, g_lnf);
    cudaGetSymbolAddress(&p_intf, g_intf);
    cudaGetSymbolAddress(&p_wtp, g_wtp);
    cudaGetSymbolAddress(&p_w1p, g_w1p);
    cudaGetSymbolAddress(&p_w2p, g_w2p);
    cudaGetSymbolAddress((void**)&p_hres, g_hres);

    static cudaStream_t s1 = nullptr;
    static cudaEvent_t ev_fork = nullptr, ev_join = nullptr;
    if (s1 == nullptr) {
        cudaStreamCreateWithFlags(&s1, cudaStreamNonBlocking);
        cudaEventCreateWithFlags(&ev_fork, cudaEventDisableTiming);
        cudaEventCreateWithFlags(&ev_join, cudaEventDisableTiming);
    }

    cudaEventRecord(ev_fork, 0);
    cudaStreamWaitEvent(s1, ev_fork, 0);

    prep_kernel<<<(64 * 1024 + 8192 + 255) / 256, 256>>>(wfc, W1, W2);  // 1 (main)
    deg_kernel<<<(EE + 255) / 256, 256, 0, s1>>>(edst);                 // 2 (s1)
    scan1_kernel<<<NBLK_SCAN, 256, 0, s1>>>();                          // 3 (s1)

    // z = x @ WT  (A f32, C half row-major)   — launch 4 = profiled slot
    {
        dim3 grid(NTILES, 1);
        tgemm_kernel<0, 0, 1><<<grid, 256>>>(x, (const uint32_t*)p_wtp, p_zh,
                                             NN, DD, DD, nullptr, nullptr);
    }
    scan2_kernel<<<1, 256, 0, s1>>>();                                  // 5 (s1)
    eler_kernel<<<(NN * HH + 255) / 256, 256>>>(a_l, a_r);              // 6 (main)

    cudaEventRecord(ev_join, s1);
    cudaStreamWaitEvent(0, ev_join, 0);

    scatter_kernel<<<(EE + 255) / 256, 256>>>(esrc, edst);              // 7
    agg_ln_kernel<<<(NN + 7) / 8, 256>>>(x, gamma, beta);               // 8

    // inter = relu(ln @ W1 + b1)  (A frag, C frag for GEMM3)
    {
        dim3 grid(NTILES, DFF / 128);
        tgemm_kernel<1, 1, 2><<<grid, 256>>>(p_lnf, (const uint32_t*)p_w1p, p_intf,
                                             NN, DFF, DD, b1, nullptr);
    }
    // out = inter @ W2 + b2 + hres  (A frag, C f32 row-major)
    {
        dim3 grid(NTILES, 1);
        tgemm_kernel<2, 1, 0><<<grid, 256>>>(p_intf, (const uint32_t*)p_w2p, out,
                                             NN, DD, DFF, b2, p_hres);
    }
}